// round 7
// baseline (speedup 1.0000x reference)
#include <cuda_runtime.h>
#include <cstdint>
#include <mma.h>
#include <math.h>

using namespace nvcuda;

// ---------------------------------------------------------------------------
// EncoderBlock: B=8, N=1024, E=768, H=8, d=96
// tf32 tensor-core version, cp.async double-buffered GEMMs.
// ---------------------------------------------------------------------------

#define Bb    8
#define SEQ   1024
#define EMB   768
#define HEADS 8
#define HD    96
#define MROWS (Bb * SEQ)     // 8192
#define E4    (4 * EMB)      // 3072
#define BH    (Bb * HEADS)   // 64

// Scratch (static device globals)
__device__ float g_qkvr  [(size_t)MROWS * E4];   // also reused as AV-raw scratch
__device__ float g_q     [(size_t)BH * SEQ * HD];
__device__ float g_k     [(size_t)BH * SEQ * HD];
__device__ float g_v     [(size_t)BH * SEQ * HD];
__device__ float g_r     [(size_t)BH * SEQ * HD];
__device__ float g_att   [(size_t)BH * SEQ * SEQ];
__device__ float g_attout[(size_t)MROWS * EMB];
__device__ float g_proj  [(size_t)MROWS * EMB];
__device__ float g_x1    [(size_t)MROWS * EMB];
__device__ float g_ffh   [(size_t)MROWS * E4];
__device__ float g_ff    [(size_t)MROWS * EMB];

// ---------------------------------------------------------------------------
// cp.async helpers
// ---------------------------------------------------------------------------
__device__ __forceinline__ void cp_async16(void* smem_dst, const void* gsrc) {
    unsigned int s = (unsigned int)__cvta_generic_to_shared(smem_dst);
    asm volatile("cp.async.cg.shared.global [%0], [%1], 16;\n" :: "r"(s), "l"(gsrc));
}
__device__ __forceinline__ void cp_commit() {
    asm volatile("cp.async.commit_group;\n");
}
__device__ __forceinline__ void cp_wait1() {
    asm volatile("cp.async.wait_group 1;\n");
}
__device__ __forceinline__ void cp_wait0() {
    asm volatile("cp.async.wait_group 0;\n");
}

// ---------------------------------------------------------------------------
// tf32 GEMM: C[M,N] = A[M,K] @ W[K,N]  (raw product; bias folded downstream)
// 128x128 block tile, BK=16, double-buffered cp.async, 8 warps (32x64 each).
// NOTE: fp32 values fed to tf32 MMA directly (HW truncates low mantissa bits).
// ---------------------------------------------------------------------------
__global__ __launch_bounds__(256) void gemm_tf32(
    const float* __restrict__ A, const float* __restrict__ W,
    float* __restrict__ C, int Md, int Nd, int Kd)
{
    __shared__ float As[2][128][20];   // A[m][k], 4-float pad
    __shared__ float Bs[2][16][132];   // W[k][n], 4-float pad

    const int tid = threadIdx.x;
    const int warpId = tid >> 5;
    const int warpM = warpId >> 1;      // 0..3  -> 32 rows
    const int warpN = warpId & 1;       // 0..1  -> 64 cols
    const int rowStart = blockIdx.y * 128;
    const int colStart = blockIdx.x * 128;

    wmma::fragment<wmma::accumulator, 16, 16, 8, float> acc[2][4];
#pragma unroll
    for (int i = 0; i < 2; i++)
#pragma unroll
        for (int j = 0; j < 4; j++) wmma::fill_fragment(acc[i][j], 0.0f);

    const int ntiles = Kd >> 4;

    // ---- async load of tile t into buffer buf ----
    auto load_tile = [&](int t, int buf) {
        int kt = t << 4;
        // A tile 128x16 = 512 float4 chunks, 2 per thread
#pragma unroll
        for (int l = 0; l < 2; l++) {
            int idx = tid + l * 256;
            int row = idx >> 2;
            int k4  = (idx & 3) * 4;
            cp_async16(&As[buf][row][k4],
                       &A[(size_t)(rowStart + row) * Kd + kt + k4]);
        }
        // W tile 16x128 = 512 chunks, 2 per thread
#pragma unroll
        for (int l = 0; l < 2; l++) {
            int idx = tid + l * 256;
            int kr = idx >> 5;
            int c4 = (idx & 31) * 4;
            cp_async16(&Bs[buf][kr][c4],
                       &W[(size_t)(kt + kr) * Nd + colStart + c4]);
        }
        cp_commit();
    };

    load_tile(0, 0);

    for (int t = 0; t < ntiles; t++) {
        if (t + 1 < ntiles) { load_tile(t + 1, (t + 1) & 1); cp_wait1(); }
        else                { cp_wait0(); }
        __syncthreads();

        const int buf = t & 1;
#pragma unroll
        for (int kk = 0; kk < 16; kk += 8) {
            wmma::fragment<wmma::matrix_a, 16, 16, 8, wmma::precision::tf32, wmma::row_major> af[2];
            wmma::fragment<wmma::matrix_b, 16, 16, 8, wmma::precision::tf32, wmma::row_major> bf[4];
#pragma unroll
            for (int i = 0; i < 2; i++)
                wmma::load_matrix_sync(af[i], &As[buf][warpM * 32 + i * 16][kk], 20);
#pragma unroll
            for (int j = 0; j < 4; j++)
                wmma::load_matrix_sync(bf[j], &Bs[buf][kk][warpN * 64 + j * 16], 132);
#pragma unroll
            for (int i = 0; i < 2; i++)
#pragma unroll
                for (int j = 0; j < 4; j++)
                    wmma::mma_sync(acc[i][j], af[i], bf[j], acc[i][j]);
        }
        __syncthreads();
    }

#pragma unroll
    for (int i = 0; i < 2; i++)
#pragma unroll
        for (int j = 0; j < 4; j++)
            wmma::store_matrix_sync(
                &C[(size_t)(rowStart + warpM * 32 + i * 16) * Nd +
                   colStart + warpN * 64 + j * 16],
                acc[i][j], Nd, wmma::mem_row_major);
}

// ---------------------------------------------------------------------------
// energy[bh][i][j] = Q[bh][i][:] . K[bh][j][:]   (GEMM-NT, Kdim=96, tf32)
// ---------------------------------------------------------------------------
__global__ __launch_bounds__(256) void attn_energy_tf32(
    const float* __restrict__ Q, const float* __restrict__ K,
    float* __restrict__ Eout)
{
    __shared__ float Qs[2][128][20];
    __shared__ float Ks[2][128][20];

    const int tid = threadIdx.x;
    const int warpId = tid >> 5;
    const int warpM = warpId >> 1;
    const int warpN = warpId & 1;
    const int rowStart = blockIdx.y * 128;
    const int colStart = blockIdx.x * 128;
    const int bh = blockIdx.z;

    const float* Qb = Q + (size_t)bh * SEQ * HD;
    const float* Kb = K + (size_t)bh * SEQ * HD;

    wmma::fragment<wmma::accumulator, 16, 16, 8, float> acc[2][4];
#pragma unroll
    for (int i = 0; i < 2; i++)
#pragma unroll
        for (int j = 0; j < 4; j++) wmma::fill_fragment(acc[i][j], 0.0f);

    const int ntiles = HD >> 4;   // 6

    auto load_tile = [&](int t, int buf) {
        int kt = t << 4;
#pragma unroll
        for (int l = 0; l < 2; l++) {
            int idx = tid + l * 256;
            int row = idx >> 2;
            int k4  = (idx & 3) * 4;
            cp_async16(&Qs[buf][row][k4],
                       &Qb[(size_t)(rowStart + row) * HD + kt + k4]);
            cp_async16(&Ks[buf][row][k4],
                       &Kb[(size_t)(colStart + row) * HD + kt + k4]);
        }
        cp_commit();
    };

    load_tile(0, 0);

    for (int t = 0; t < ntiles; t++) {
        if (t + 1 < ntiles) { load_tile(t + 1, (t + 1) & 1); cp_wait1(); }
        else                { cp_wait0(); }
        __syncthreads();

        const int buf = t & 1;
#pragma unroll
        for (int kk = 0; kk < 16; kk += 8) {
            wmma::fragment<wmma::matrix_a, 16, 16, 8, wmma::precision::tf32, wmma::row_major> af[2];
            wmma::fragment<wmma::matrix_b, 16, 16, 8, wmma::precision::tf32, wmma::col_major> bf[4];
#pragma unroll
            for (int i = 0; i < 2; i++)
                wmma::load_matrix_sync(af[i], &Qs[buf][warpM * 32 + i * 16][kk], 20);
#pragma unroll
            for (int j = 0; j < 4; j++)
                wmma::load_matrix_sync(bf[j], &Ks[buf][warpN * 64 + j * 16][kk], 20);
#pragma unroll
            for (int i = 0; i < 2; i++)
#pragma unroll
                for (int j = 0; j < 4; j++)
                    wmma::mma_sync(acc[i][j], af[i], bf[j], acc[i][j]);
        }
        __syncthreads();
    }

    float* Eb = Eout + (size_t)bh * SEQ * SEQ;
#pragma unroll
    for (int i = 0; i < 2; i++)
#pragma unroll
        for (int j = 0; j < 4; j++)
            wmma::store_matrix_sync(
                &Eb[(size_t)(rowStart + warpM * 32 + i * 16) * SEQ +
                    colStart + warpN * 64 + j * 16],
                acc[i][j], SEQ, wmma::mem_row_major);
}

// ---------------------------------------------------------------------------
// avraw[bh][n][d] = att[bh][n][:] @ V[bh][:][d]   (M=1024, N=96, K=1024)
// 128x96 tile, warp tile 32x48, double-buffered.
// ---------------------------------------------------------------------------
__global__ __launch_bounds__(256) void attn_av_tf32(
    const float* __restrict__ att, const float* __restrict__ V,
    float* __restrict__ avraw)
{
    __shared__ float As[2][128][20];
    __shared__ float Bs[2][16][100];

    const int tid = threadIdx.x;
    const int warpId = tid >> 5;
    const int warpM = warpId >> 1;      // 0..3
    const int warpN = warpId & 1;       // 0..1 -> 48 cols
    const int rowStart = blockIdx.y * 128;
    const int bh = blockIdx.z;

    const float* Ab = att + (size_t)bh * SEQ * SEQ;
    const float* Vb = V + (size_t)bh * SEQ * HD;

    wmma::fragment<wmma::accumulator, 16, 16, 8, float> acc[2][3];
#pragma unroll
    for (int i = 0; i < 2; i++)
#pragma unroll
        for (int j = 0; j < 3; j++) wmma::fill_fragment(acc[i][j], 0.0f);

    const int ntiles = SEQ >> 4;   // 64

    auto load_tile = [&](int t, int buf) {
        int kt = t << 4;
#pragma unroll
        for (int l = 0; l < 2; l++) {
            int idx = tid + l * 256;
            int row = idx >> 2;
            int k4  = (idx & 3) * 4;
            cp_async16(&As[buf][row][k4],
                       &Ab[(size_t)(rowStart + row) * SEQ + kt + k4]);
        }
        // V tile 16x96 = 384 float4 chunks
        for (int idx = tid; idx < 384; idx += 256) {
            int kr = idx / 24;
            int c4 = (idx % 24) * 4;
            cp_async16(&Bs[buf][kr][c4],
                       &Vb[(size_t)(kt + kr) * HD + c4]);
        }
        cp_commit();
    };

    load_tile(0, 0);

    for (int t = 0; t < ntiles; t++) {
        if (t + 1 < ntiles) { load_tile(t + 1, (t + 1) & 1); cp_wait1(); }
        else                { cp_wait0(); }
        __syncthreads();

        const int buf = t & 1;
#pragma unroll
        for (int kk = 0; kk < 16; kk += 8) {
            wmma::fragment<wmma::matrix_a, 16, 16, 8, wmma::precision::tf32, wmma::row_major> af[2];
            wmma::fragment<wmma::matrix_b, 16, 16, 8, wmma::precision::tf32, wmma::row_major> bf[3];
#pragma unroll
            for (int i = 0; i < 2; i++)
                wmma::load_matrix_sync(af[i], &As[buf][warpM * 32 + i * 16][kk], 20);
#pragma unroll
            for (int j = 0; j < 3; j++)
                wmma::load_matrix_sync(bf[j], &Bs[buf][kk][warpN * 48 + j * 16], 100);
#pragma unroll
            for (int i = 0; i < 2; i++)
#pragma unroll
                for (int j = 0; j < 3; j++)
                    wmma::mma_sync(acc[i][j], af[i], bf[j], acc[i][j]);
        }
        __syncthreads();
    }

    float* Sb = avraw + (size_t)bh * SEQ * HD;
#pragma unroll
    for (int i = 0; i < 2; i++)
#pragma unroll
        for (int j = 0; j < 3; j++)
            wmma::store_matrix_sync(
                &Sb[(size_t)(rowStart + warpM * 32 + i * 16) * HD +
                    warpN * 48 + j * 16],
                acc[i][j], HD, wmma::mem_row_major);
}

// ---------------------------------------------------------------------------
// Unpack qkvr raw [8192,3072] (+bias) -> q/k/v/r [bh=64][1024][96]
// ---------------------------------------------------------------------------
__global__ void unpack_qkvr(const float* __restrict__ qkvr,
                            const float* __restrict__ bias)
{
    const size_t total = (size_t)MROWS * E4;
    for (size_t idx = (size_t)blockIdx.x * blockDim.x + threadIdx.x;
         idx < total; idx += (size_t)gridDim.x * blockDim.x) {
        int row = (int)(idx / E4);
        int col = (int)(idx % E4);
        int s  = col & 3;
        int t  = col >> 2;
        int h  = t / HD;
        int dd = t - h * HD;
        int b  = row >> 10;
        int n  = row & 1023;
        size_t dst = ((size_t)(b * HEADS + h) * SEQ + n) * HD + dd;
        float val = qkvr[idx] + bias[col];
        if      (s == 0) g_q[dst] = val;
        else if (s == 1) g_k[dst] = val;
        else if (s == 2) g_v[dst] = val;
        else             g_r[dst] = val;
    }
}

// ---------------------------------------------------------------------------
// Row softmax of UNSCALED logits, then /sqrt(EMB). Coalesced float4.
// ---------------------------------------------------------------------------
__global__ __launch_bounds__(128) void softmax_scale(float* __restrict__ att)
{
    __shared__ float red[128];
    const int tid = threadIdx.x;
    float4* rowp = (float4*)(att + (size_t)blockIdx.x * SEQ);

    float4 a = rowp[tid];
    float4 b = rowp[tid + 128];
    float m = fmaxf(fmaxf(fmaxf(a.x, a.y), fmaxf(a.z, a.w)),
                    fmaxf(fmaxf(b.x, b.y), fmaxf(b.z, b.w)));
    red[tid] = m;
    __syncthreads();
    for (int off = 64; off > 0; off >>= 1) {
        if (tid < off) red[tid] = fmaxf(red[tid], red[tid + off]);
        __syncthreads();
    }
    m = red[0];
    __syncthreads();

    a.x = expf(a.x - m); a.y = expf(a.y - m); a.z = expf(a.z - m); a.w = expf(a.w - m);
    b.x = expf(b.x - m); b.y = expf(b.y - m); b.z = expf(b.z - m); b.w = expf(b.w - m);
    float s = a.x + a.y + a.z + a.w + b.x + b.y + b.z + b.w;
    red[tid] = s;
    __syncthreads();
    for (int off = 64; off > 0; off >>= 1) {
        if (tid < off) red[tid] += red[tid + off];
        __syncthreads();
    }
    const float inv = 1.0f / (red[0] * 27.712812921102035f);   // sum * sqrt(768)
    a.x *= inv; a.y *= inv; a.z *= inv; a.w *= inv;
    b.x *= inv; b.y *= inv; b.z *= inv; b.w *= inv;
    rowp[tid] = a;
    rowp[tid + 128] = b;
}

// ---------------------------------------------------------------------------
// r-gate + head merge
// ---------------------------------------------------------------------------
__global__ __launch_bounds__(256) void rgate_merge(
    const float* __restrict__ avraw, const float* __restrict__ R,
    float* __restrict__ out)
{
    const size_t total4 = (size_t)MROWS * EMB / 4;
    for (size_t idx = (size_t)blockIdx.x * blockDim.x + threadIdx.x;
         idx < total4; idx += (size_t)gridDim.x * blockDim.x) {
        int row = (int)(idx / 192);
        int c4  = (int)(idx % 192);
        int col = c4 * 4;
        int h  = col / HD;
        int d  = col - h * HD;
        int b  = row >> 10;
        int n  = row & 1023;
        size_t src = (((size_t)(b * HEADS + h) * SEQ + n) * HD + d) / 4;
        float4 p = ((const float4*)avraw)[src];
        float4 g = ((const float4*)R)[src];
        p.x *= g.x; p.y *= g.y; p.z *= g.z; p.w *= g.w;
        ((float4*)out)[idx] = p;
    }
}

// ---------------------------------------------------------------------------
// ffh = gelu(ffh + b_ff1), exact erf
// ---------------------------------------------------------------------------
__global__ __launch_bounds__(256) void bias_gelu(
    float* __restrict__ ffh, const float* __restrict__ bias)
{
    const size_t total4 = (size_t)MROWS * E4 / 4;
    for (size_t idx = (size_t)blockIdx.x * blockDim.x + threadIdx.x;
         idx < total4; idx += (size_t)gridDim.x * blockDim.x) {
        int c4 = (int)(idx % (E4 / 4));
        float4 bv = ((const float4*)bias)[c4];
        float4 v = ((float4*)ffh)[idx];
        v.x += bv.x; v.y += bv.y; v.z += bv.z; v.w += bv.w;
        v.x = 0.5f * v.x * (1.0f + erff(v.x * 0.70710678118654752f));
        v.y = 0.5f * v.y * (1.0f + erff(v.y * 0.70710678118654752f));
        v.z = 0.5f * v.z * (1.0f + erff(v.z * 0.70710678118654752f));
        v.w = 0.5f * v.w * (1.0f + erff(v.w * 0.70710678118654752f));
        ((float4*)ffh)[idx] = v;
    }
}

// ---------------------------------------------------------------------------
// out = LayerNorm(a + bias2 + b) * g + beta
// ---------------------------------------------------------------------------
__global__ __launch_bounds__(256) void resid_ln_bias(
    const float* __restrict__ a, const float* __restrict__ bias2,
    const float* __restrict__ b,
    const float* __restrict__ g, const float* __restrict__ beta,
    float* __restrict__ out)
{
    __shared__ float red[256];
    const int tid = threadIdx.x;
    const size_t base = (size_t)blockIdx.x * EMB;

    float y[3];
    float s = 0.0f;
#pragma unroll
    for (int i = 0; i < 3; i++) {
        int j = tid + i * 256;
        y[i] = a[base + j] + bias2[j] + b[base + j];
        s += y[i];
    }
    red[tid] = s;
    __syncthreads();
    for (int off = 128; off > 0; off >>= 1) {
        if (tid < off) red[tid] += red[tid + off];
        __syncthreads();
    }
    const float mu = red[0] * (1.0f / EMB);
    __syncthreads();

    s = 0.0f;
#pragma unroll
    for (int i = 0; i < 3; i++) {
        float d = y[i] - mu;
        s += d * d;
    }
    red[tid] = s;
    __syncthreads();
    for (int off = 128; off > 0; off >>= 1) {
        if (tid < off) red[tid] += red[tid + off];
        __syncthreads();
    }
    const float inv = rsqrtf(red[0] * (1.0f / EMB) + 1e-5f);
#pragma unroll
    for (int i = 0; i < 3; i++) {
        int j = tid + i * 256;
        out[base + j] = (y[i] - mu) * inv * g[j] + beta[j];
    }
}

// ---------------------------------------------------------------------------
extern "C" void kernel_launch(void* const* d_in, const int* in_sizes, int n_in,
                              void* d_out, int out_size)
{
    (void)in_sizes; (void)n_in; (void)out_size;

    const float* x      = (const float*)d_in[0];
    const float* w_qkvr = (const float*)d_in[1];
    const float* b_qkvr = (const float*)d_in[2];
    const float* w_proj = (const float*)d_in[3];
    const float* b_proj = (const float*)d_in[4];
    const float* ln1_g  = (const float*)d_in[5];
    const float* ln1_b  = (const float*)d_in[6];
    const float* w_ff1  = (const float*)d_in[7];
    const float* b_ff1  = (const float*)d_in[8];
    const float* w_ff2  = (const float*)d_in[9];
    const float* b_ff2  = (const float*)d_in[10];
    const float* ln2_g  = (const float*)d_in[11];
    const float* ln2_b  = (const float*)d_in[12];
    float* out = (float*)d_out;

    float *qkvr, *q, *k, *v, *r, *att, *attout, *proj, *x1, *ffh, *ff;
    cudaGetSymbolAddress((void**)&qkvr,   g_qkvr);
    cudaGetSymbolAddress((void**)&q,      g_q);
    cudaGetSymbolAddress((void**)&k,      g_k);
    cudaGetSymbolAddress((void**)&v,      g_v);
    cudaGetSymbolAddress((void**)&r,      g_r);
    cudaGetSymbolAddress((void**)&att,    g_att);
    cudaGetSymbolAddress((void**)&attout, g_attout);
    cudaGetSymbolAddress((void**)&proj,   g_proj);
    cudaGetSymbolAddress((void**)&x1,     g_x1);
    cudaGetSymbolAddress((void**)&ffh,    g_ffh);
    cudaGetSymbolAddress((void**)&ff,     g_ff);

    // 1. qkvr = x @ w_qkvr (raw)
    gemm_tf32<<<dim3(E4 / 128, MROWS / 128), 256>>>(x, w_qkvr, qkvr, MROWS, E4, EMB);

    // 2. unpack (+ b_qkvr) -> q/k/v/r
    unpack_qkvr<<<4096, 256>>>(qkvr, b_qkvr);

    // 3. energy = q @ k^T (unscaled)
    attn_energy_tf32<<<dim3(SEQ / 128, SEQ / 128, BH), 256>>>(q, k, att);

    // 4. softmax / sqrt(768)
    softmax_scale<<<BH * SEQ, 128>>>(att);

    // 5. avraw = att @ v   (reuse g_qkvr as scratch)
    attn_av_tf32<<<dim3(1, SEQ / 128, BH), 256>>>(att, v, qkvr);

    // 6. attout = avraw * r, merged to [b,n,e]
    rgate_merge<<<2048, 256>>>(qkvr, r, attout);

    // 7. proj = attout @ w_proj (raw)
    gemm_tf32<<<dim3(EMB / 128, MROWS / 128), 256>>>(attout, w_proj, proj, MROWS, EMB, EMB);

    // 8. x1 = LN(proj + b_proj + x)
    resid_ln_bias<<<MROWS, 256>>>(proj, b_proj, x, ln1_g, ln1_b, x1);

    // 9. ffh = x1 @ w_ff1 (raw)
    gemm_tf32<<<dim3(E4 / 128, MROWS / 128), 256>>>(x1, w_ff1, ffh, MROWS, E4, EMB);

    // 10. ffh = gelu(ffh + b_ff1)
    bias_gelu<<<8192, 256>>>(ffh, b_ff1);

    // 11. ff = ffh @ w_ff2 (raw)
    gemm_tf32<<<dim3(EMB / 128, MROWS / 128), 256>>>(ffh, w_ff2, ff, MROWS, EMB, E4);

    // 12. out = LN(ff + b_ff2 + x1)
    resid_ln_bias<<<MROWS, 256>>>(ff, b_ff2, x1, ln2_g, ln2_b, out);
}

// round 10
// speedup vs baseline: 1.4105x; 1.4105x over previous
#include <cuda_runtime.h>
#include <cstdint>
#include <mma.h>
#include <math.h>

using namespace nvcuda;

// ---------------------------------------------------------------------------
// EncoderBlock: B=8, N=1024, E=768, H=8, d=96
// tf32 wmma, BK=32 double-buffered cp.async, dynamic smem (~70KB, 2 CTA/SM)
// ---------------------------------------------------------------------------

#define Bb    8
#define SEQ   1024
#define EMB   768
#define HEADS 8
#define HD    96
#define MROWS (Bb * SEQ)     // 8192
#define E4    (4 * EMB)      // 3072
#define BH    (Bb * HEADS)   // 64

// smem element counts
#define GEMM_SMEM_FLOATS  (2*128*36 + 2*32*132)   // 17664 -> 70656 B
#define ENER_SMEM_FLOATS  (2*128*36 + 2*128*36)   // 18432 -> 73728 B
#define AV_SMEM_FLOATS    (2*128*36 + 2*32*100)   // 15616 -> 62464 B

// Scratch (static device globals)
__device__ float g_qkvr  [(size_t)MROWS * E4];   // also reused as AV-raw scratch
__device__ float g_q     [(size_t)BH * SEQ * HD];
__device__ float g_k     [(size_t)BH * SEQ * HD];
__device__ float g_v     [(size_t)BH * SEQ * HD];
__device__ float g_r     [(size_t)BH * SEQ * HD];
__device__ float g_att   [(size_t)BH * SEQ * SEQ];
__device__ float g_attout[(size_t)MROWS * EMB];
__device__ float g_proj  [(size_t)MROWS * EMB];
__device__ float g_x1    [(size_t)MROWS * EMB];
__device__ float g_ffh   [(size_t)MROWS * E4];
__device__ float g_ff    [(size_t)MROWS * EMB];

// ---------------------------------------------------------------------------
// cp.async helpers
// ---------------------------------------------------------------------------
__device__ __forceinline__ void cp_async16(void* smem_dst, const void* gsrc) {
    unsigned int s = (unsigned int)__cvta_generic_to_shared(smem_dst);
    asm volatile("cp.async.cg.shared.global [%0], [%1], 16;\n" :: "r"(s), "l"(gsrc));
}
__device__ __forceinline__ void cp_commit() {
    asm volatile("cp.async.commit_group;\n");
}
__device__ __forceinline__ void cp_wait1() {
    asm volatile("cp.async.wait_group 1;\n");
}
__device__ __forceinline__ void cp_wait0() {
    asm volatile("cp.async.wait_group 0;\n");
}

// ---------------------------------------------------------------------------
// tf32 GEMM: C[M,N] = A[M,K] @ W[K,N] (raw product; bias folded downstream)
// 128x128 block tile, BK=32, 2-stage cp.async, 8 warps (32x64 each).
// fp32 fed to tf32 MMA directly (HW truncates low mantissa bits).
// ---------------------------------------------------------------------------
__global__ __launch_bounds__(256) void gemm_tf32(
    const float* __restrict__ A, const float* __restrict__ W,
    float* __restrict__ C, int Md, int Nd, int Kd)
{
    extern __shared__ float smem[];
    // As: 2 stages of [128][36]; Bs: 2 stages of [32][132]
    float (*As)[128][36] = reinterpret_cast<float(*)[128][36]>(smem);
    float (*Bs)[32][132] = reinterpret_cast<float(*)[32][132]>(smem + 2*128*36);

    const int tid = threadIdx.x;
    const int warpId = tid >> 5;
    const int warpM = warpId >> 1;      // 0..3  -> 32 rows
    const int warpN = warpId & 1;       // 0..1  -> 64 cols
    const int rowStart = blockIdx.y * 128;
    const int colStart = blockIdx.x * 128;

    wmma::fragment<wmma::accumulator, 16, 16, 8, float> acc[2][4];
#pragma unroll
    for (int i = 0; i < 2; i++)
#pragma unroll
        for (int j = 0; j < 4; j++) wmma::fill_fragment(acc[i][j], 0.0f);

    const int ntiles = Kd >> 5;

    auto load_tile = [&](int t, int buf) {
        int kt = t << 5;
        // A tile 128x32 = 1024 float4 chunks, 4/thread
#pragma unroll
        for (int l = 0; l < 4; l++) {
            int idx = tid + l * 256;
            int row = idx >> 3;
            int k4  = (idx & 7) * 4;
            cp_async16(&As[buf][row][k4],
                       &A[(size_t)(rowStart + row) * Kd + kt + k4]);
        }
        // W tile 32x128 = 1024 chunks, 4/thread
#pragma unroll
        for (int l = 0; l < 4; l++) {
            int idx = tid + l * 256;
            int kr = idx >> 5;
            int c4 = (idx & 31) * 4;
            cp_async16(&Bs[buf][kr][c4],
                       &W[(size_t)(kt + kr) * Nd + colStart + c4]);
        }
        cp_commit();
    };

    load_tile(0, 0);

    for (int t = 0; t < ntiles; t++) {
        if (t + 1 < ntiles) { load_tile(t + 1, (t + 1) & 1); cp_wait1(); }
        else                { cp_wait0(); }
        __syncthreads();

        const int buf = t & 1;
#pragma unroll
        for (int kk = 0; kk < 32; kk += 8) {
            wmma::fragment<wmma::matrix_a, 16, 16, 8, wmma::precision::tf32, wmma::row_major> af[2];
            wmma::fragment<wmma::matrix_b, 16, 16, 8, wmma::precision::tf32, wmma::row_major> bf[4];
#pragma unroll
            for (int i = 0; i < 2; i++)
                wmma::load_matrix_sync(af[i], &As[buf][warpM * 32 + i * 16][kk], 36);
#pragma unroll
            for (int j = 0; j < 4; j++)
                wmma::load_matrix_sync(bf[j], &Bs[buf][kk][warpN * 64 + j * 16], 132);
#pragma unroll
            for (int i = 0; i < 2; i++)
#pragma unroll
                for (int j = 0; j < 4; j++)
                    wmma::mma_sync(acc[i][j], af[i], bf[j], acc[i][j]);
        }
        __syncthreads();
    }

#pragma unroll
    for (int i = 0; i < 2; i++)
#pragma unroll
        for (int j = 0; j < 4; j++)
            wmma::store_matrix_sync(
                &C[(size_t)(rowStart + warpM * 32 + i * 16) * Nd +
                   colStart + warpN * 64 + j * 16],
                acc[i][j], Nd, wmma::mem_row_major);
}

// ---------------------------------------------------------------------------
// energy[bh][i][j] = Q[bh][i][:] . K[bh][j][:]   (GEMM-NT, Kdim=96, tf32)
// BK=32, 3 iterations, 2-stage.
// ---------------------------------------------------------------------------
__global__ __launch_bounds__(256) void attn_energy_tf32(
    const float* __restrict__ Q, const float* __restrict__ K,
    float* __restrict__ Eout)
{
    extern __shared__ float smem[];
    float (*Qs)[128][36] = reinterpret_cast<float(*)[128][36]>(smem);
    float (*Ks)[128][36] = reinterpret_cast<float(*)[128][36]>(smem + 2*128*36);

    const int tid = threadIdx.x;
    const int warpId = tid >> 5;
    const int warpM = warpId >> 1;
    const int warpN = warpId & 1;
    const int rowStart = blockIdx.y * 128;
    const int colStart = blockIdx.x * 128;
    const int bh = blockIdx.z;

    const float* Qb = Q + (size_t)bh * SEQ * HD;
    const float* Kb = K + (size_t)bh * SEQ * HD;

    wmma::fragment<wmma::accumulator, 16, 16, 8, float> acc[2][4];
#pragma unroll
    for (int i = 0; i < 2; i++)
#pragma unroll
        for (int j = 0; j < 4; j++) wmma::fill_fragment(acc[i][j], 0.0f);

    const int ntiles = HD >> 5;   // 3

    auto load_tile = [&](int t, int buf) {
        int kt = t << 5;
#pragma unroll
        for (int l = 0; l < 4; l++) {
            int idx = tid + l * 256;
            int row = idx >> 3;
            int k4  = (idx & 7) * 4;
            cp_async16(&Qs[buf][row][k4],
                       &Qb[(size_t)(rowStart + row) * HD + kt + k4]);
            cp_async16(&Ks[buf][row][k4],
                       &Kb[(size_t)(colStart + row) * HD + kt + k4]);
        }
        cp_commit();
    };

    load_tile(0, 0);

    for (int t = 0; t < ntiles; t++) {
        if (t + 1 < ntiles) { load_tile(t + 1, (t + 1) & 1); cp_wait1(); }
        else                { cp_wait0(); }
        __syncthreads();

        const int buf = t & 1;
#pragma unroll
        for (int kk = 0; kk < 32; kk += 8) {
            wmma::fragment<wmma::matrix_a, 16, 16, 8, wmma::precision::tf32, wmma::row_major> af[2];
            wmma::fragment<wmma::matrix_b, 16, 16, 8, wmma::precision::tf32, wmma::col_major> bf[4];
#pragma unroll
            for (int i = 0; i < 2; i++)
                wmma::load_matrix_sync(af[i], &Qs[buf][warpM * 32 + i * 16][kk], 36);
#pragma unroll
            for (int j = 0; j < 4; j++)
                wmma::load_matrix_sync(bf[j], &Ks[buf][warpN * 64 + j * 16][kk], 36);
#pragma unroll
            for (int i = 0; i < 2; i++)
#pragma unroll
                for (int j = 0; j < 4; j++)
                    wmma::mma_sync(acc[i][j], af[i], bf[j], acc[i][j]);
        }
        __syncthreads();
    }

    float* Eb = Eout + (size_t)bh * SEQ * SEQ;
#pragma unroll
    for (int i = 0; i < 2; i++)
#pragma unroll
        for (int j = 0; j < 4; j++)
            wmma::store_matrix_sync(
                &Eb[(size_t)(rowStart + warpM * 32 + i * 16) * SEQ +
                    colStart + warpN * 64 + j * 16],
                acc[i][j], SEQ, wmma::mem_row_major);
}

// ---------------------------------------------------------------------------
// avraw[bh][n][d] = att[bh][n][:] @ V[bh][:][d]   (M=1024, N=96, K=1024)
// 128x96 tile, warp 32x48, BK=32, 2-stage.
// ---------------------------------------------------------------------------
__global__ __launch_bounds__(256) void attn_av_tf32(
    const float* __restrict__ att, const float* __restrict__ V,
    float* __restrict__ avraw)
{
    extern __shared__ float smem[];
    float (*As)[128][36] = reinterpret_cast<float(*)[128][36]>(smem);
    float (*Bs)[32][100] = reinterpret_cast<float(*)[32][100]>(smem + 2*128*36);

    const int tid = threadIdx.x;
    const int warpId = tid >> 5;
    const int warpM = warpId >> 1;      // 0..3
    const int warpN = warpId & 1;       // 0..1 -> 48 cols
    const int rowStart = blockIdx.y * 128;
    const int bh = blockIdx.z;

    const float* Ab = att + (size_t)bh * SEQ * SEQ;
    const float* Vb = V + (size_t)bh * SEQ * HD;

    wmma::fragment<wmma::accumulator, 16, 16, 8, float> acc[2][3];
#pragma unroll
    for (int i = 0; i < 2; i++)
#pragma unroll
        for (int j = 0; j < 3; j++) wmma::fill_fragment(acc[i][j], 0.0f);

    const int ntiles = SEQ >> 5;   // 32

    auto load_tile = [&](int t, int buf) {
        int kt = t << 5;
#pragma unroll
        for (int l = 0; l < 4; l++) {
            int idx = tid + l * 256;
            int row = idx >> 3;
            int k4  = (idx & 7) * 4;
            cp_async16(&As[buf][row][k4],
                       &Ab[(size_t)(rowStart + row) * SEQ + kt + k4]);
        }
        // V tile 32x96 = 768 float4 chunks, 3/thread
#pragma unroll
        for (int l = 0; l < 3; l++) {
            int idx = tid + l * 256;
            int kr = idx / 24;
            int c4 = (idx % 24) * 4;
            cp_async16(&Bs[buf][kr][c4],
                       &Vb[(size_t)(kt + kr) * HD + c4]);
        }
        cp_commit();
    };

    load_tile(0, 0);

    for (int t = 0; t < ntiles; t++) {
        if (t + 1 < ntiles) { load_tile(t + 1, (t + 1) & 1); cp_wait1(); }
        else                { cp_wait0(); }
        __syncthreads();

        const int buf = t & 1;
#pragma unroll
        for (int kk = 0; kk < 32; kk += 8) {
            wmma::fragment<wmma::matrix_a, 16, 16, 8, wmma::precision::tf32, wmma::row_major> af[2];
            wmma::fragment<wmma::matrix_b, 16, 16, 8, wmma::precision::tf32, wmma::row_major> bf[3];
#pragma unroll
            for (int i = 0; i < 2; i++)
                wmma::load_matrix_sync(af[i], &As[buf][warpM * 32 + i * 16][kk], 36);
#pragma unroll
            for (int j = 0; j < 3; j++)
                wmma::load_matrix_sync(bf[j], &Bs[buf][kk][warpN * 48 + j * 16], 100);
#pragma unroll
            for (int i = 0; i < 2; i++)
#pragma unroll
                for (int j = 0; j < 3; j++)
                    wmma::mma_sync(acc[i][j], af[i], bf[j], acc[i][j]);
        }
        __syncthreads();
    }

    float* Sb = avraw + (size_t)bh * SEQ * HD;
#pragma unroll
    for (int i = 0; i < 2; i++)
#pragma unroll
        for (int j = 0; j < 3; j++)
            wmma::store_matrix_sync(
                &Sb[(size_t)(rowStart + warpM * 32 + i * 16) * HD +
                    warpN * 48 + j * 16],
                acc[i][j], HD, wmma::mem_row_major);
}

// ---------------------------------------------------------------------------
// Unpack qkvr raw [8192,3072] (+bias) -> q/k/v/r [bh=64][1024][96]
// ---------------------------------------------------------------------------
__global__ void unpack_qkvr(const float* __restrict__ qkvr,
                            const float* __restrict__ bias)
{
    const size_t total = (size_t)MROWS * E4;
    for (size_t idx = (size_t)blockIdx.x * blockDim.x + threadIdx.x;
         idx < total; idx += (size_t)gridDim.x * blockDim.x) {
        int row = (int)(idx / E4);
        int col = (int)(idx % E4);
        int s  = col & 3;
        int t  = col >> 2;
        int h  = t / HD;
        int dd = t - h * HD;
        int b  = row >> 10;
        int n  = row & 1023;
        size_t dst = ((size_t)(b * HEADS + h) * SEQ + n) * HD + dd;
        float val = qkvr[idx] + bias[col];
        if      (s == 0) g_q[dst] = val;
        else if (s == 1) g_k[dst] = val;
        else if (s == 2) g_v[dst] = val;
        else             g_r[dst] = val;
    }
}

// ---------------------------------------------------------------------------
// Row softmax of UNSCALED logits, then /sqrt(EMB). Coalesced float4.
// ---------------------------------------------------------------------------
__global__ __launch_bounds__(128) void softmax_scale(float* __restrict__ att)
{
    __shared__ float red[128];
    const int tid = threadIdx.x;
    float4* rowp = (float4*)(att + (size_t)blockIdx.x * SEQ);

    float4 a = rowp[tid];
    float4 b = rowp[tid + 128];
    float m = fmaxf(fmaxf(fmaxf(a.x, a.y), fmaxf(a.z, a.w)),
                    fmaxf(fmaxf(b.x, b.y), fmaxf(b.z, b.w)));
    red[tid] = m;
    __syncthreads();
    for (int off = 64; off > 0; off >>= 1) {
        if (tid < off) red[tid] = fmaxf(red[tid], red[tid + off]);
        __syncthreads();
    }
    m = red[0];
    __syncthreads();

    a.x = expf(a.x - m); a.y = expf(a.y - m); a.z = expf(a.z - m); a.w = expf(a.w - m);
    b.x = expf(b.x - m); b.y = expf(b.y - m); b.z = expf(b.z - m); b.w = expf(b.w - m);
    float s = a.x + a.y + a.z + a.w + b.x + b.y + b.z + b.w;
    red[tid] = s;
    __syncthreads();
    for (int off = 64; off > 0; off >>= 1) {
        if (tid < off) red[tid] += red[tid + off];
        __syncthreads();
    }
    const float inv = 1.0f / (red[0] * 27.712812921102035f);   // sum * sqrt(768)
    a.x *= inv; a.y *= inv; a.z *= inv; a.w *= inv;
    b.x *= inv; b.y *= inv; b.z *= inv; b.w *= inv;
    rowp[tid] = a;
    rowp[tid + 128] = b;
}

// ---------------------------------------------------------------------------
// r-gate + head merge
// ---------------------------------------------------------------------------
__global__ __launch_bounds__(256) void rgate_merge(
    const float* __restrict__ avraw, const float* __restrict__ R,
    float* __restrict__ out)
{
    const size_t total4 = (size_t)MROWS * EMB / 4;
    for (size_t idx = (size_t)blockIdx.x * blockDim.x + threadIdx.x;
         idx < total4; idx += (size_t)gridDim.x * blockDim.x) {
        int row = (int)(idx / 192);
        int c4  = (int)(idx % 192);
        int col = c4 * 4;
        int h  = col / HD;
        int d  = col - h * HD;
        int b  = row >> 10;
        int n  = row & 1023;
        size_t src = (((size_t)(b * HEADS + h) * SEQ + n) * HD + d) / 4;
        float4 p = ((const float4*)avraw)[src];
        float4 g = ((const float4*)R)[src];
        p.x *= g.x; p.y *= g.y; p.z *= g.z; p.w *= g.w;
        ((float4*)out)[idx] = p;
    }
}

// ---------------------------------------------------------------------------
// ffh = gelu(ffh + b_ff1), exact erf
// ---------------------------------------------------------------------------
__global__ __launch_bounds__(256) void bias_gelu(
    float* __restrict__ ffh, const float* __restrict__ bias)
{
    const size_t total4 = (size_t)MROWS * E4 / 4;
    for (size_t idx = (size_t)blockIdx.x * blockDim.x + threadIdx.x;
         idx < total4; idx += (size_t)gridDim.x * blockDim.x) {
        int c4 = (int)(idx % (E4 / 4));
        float4 bv = ((const float4*)bias)[c4];
        float4 v = ((float4*)ffh)[idx];
        v.x += bv.x; v.y += bv.y; v.z += bv.z; v.w += bv.w;
        v.x = 0.5f * v.x * (1.0f + erff(v.x * 0.70710678118654752f));
        v.y = 0.5f * v.y * (1.0f + erff(v.y * 0.70710678118654752f));
        v.z = 0.5f * v.z * (1.0f + erff(v.z * 0.70710678118654752f));
        v.w = 0.5f * v.w * (1.0f + erff(v.w * 0.70710678118654752f));
        ((float4*)ffh)[idx] = v;
    }
}

// ---------------------------------------------------------------------------
// out = LayerNorm(a + bias2 + b) * g + beta
// ---------------------------------------------------------------------------
__global__ __launch_bounds__(256) void resid_ln_bias(
    const float* __restrict__ a, const float* __restrict__ bias2,
    const float* __restrict__ b,
    const float* __restrict__ g, const float* __restrict__ beta,
    float* __restrict__ out)
{
    __shared__ float red[256];
    const int tid = threadIdx.x;
    const size_t base = (size_t)blockIdx.x * EMB;

    float y[3];
    float s = 0.0f;
#pragma unroll
    for (int i = 0; i < 3; i++) {
        int j = tid + i * 256;
        y[i] = a[base + j] + bias2[j] + b[base + j];
        s += y[i];
    }
    red[tid] = s;
    __syncthreads();
    for (int off = 128; off > 0; off >>= 1) {
        if (tid < off) red[tid] += red[tid + off];
        __syncthreads();
    }
    const float mu = red[0] * (1.0f / EMB);
    __syncthreads();

    s = 0.0f;
#pragma unroll
    for (int i = 0; i < 3; i++) {
        float d = y[i] - mu;
        s += d * d;
    }
    red[tid] = s;
    __syncthreads();
    for (int off = 128; off > 0; off >>= 1) {
        if (tid < off) red[tid] += red[tid + off];
        __syncthreads();
    }
    const float inv = rsqrtf(red[0] * (1.0f / EMB) + 1e-5f);
#pragma unroll
    for (int i = 0; i < 3; i++) {
        int j = tid + i * 256;
        out[base + j] = (y[i] - mu) * inv * g[j] + beta[j];
    }
}

// ---------------------------------------------------------------------------
extern "C" void kernel_launch(void* const* d_in, const int* in_sizes, int n_in,
                              void* d_out, int out_size)
{
    (void)in_sizes; (void)n_in; (void)out_size;

    const float* x      = (const float*)d_in[0];
    const float* w_qkvr = (const float*)d_in[1];
    const float* b_qkvr = (const float*)d_in[2];
    const float* w_proj = (const float*)d_in[3];
    const float* b_proj = (const float*)d_in[4];
    const float* ln1_g  = (const float*)d_in[5];
    const float* ln1_b  = (const float*)d_in[6];
    const float* w_ff1  = (const float*)d_in[7];
    const float* b_ff1  = (const float*)d_in[8];
    const float* w_ff2  = (const float*)d_in[9];
    const float* b_ff2  = (const float*)d_in[10];
    const float* ln2_g  = (const float*)d_in[11];
    const float* ln2_b  = (const float*)d_in[12];
    float* out = (float*)d_out;

    float *qkvr, *q, *k, *v, *r, *att, *attout, *proj, *x1, *ffh, *ff;
    cudaGetSymbolAddress((void**)&qkvr,   g_qkvr);
    cudaGetSymbolAddress((void**)&q,      g_q);
    cudaGetSymbolAddress((void**)&k,      g_k);
    cudaGetSymbolAddress((void**)&v,      g_v);
    cudaGetSymbolAddress((void**)&r,      g_r);
    cudaGetSymbolAddress((void**)&att,    g_att);
    cudaGetSymbolAddress((void**)&attout, g_attout);
    cudaGetSymbolAddress((void**)&proj,   g_proj);
    cudaGetSymbolAddress((void**)&x1,     g_x1);
    cudaGetSymbolAddress((void**)&ffh,    g_ffh);
    cudaGetSymbolAddress((void**)&ff,     g_ff);

    const int gemmSmem = GEMM_SMEM_FLOATS * 4;   // 70656 B
    const int enerSmem = ENER_SMEM_FLOATS * 4;   // 73728 B
    const int avSmem   = AV_SMEM_FLOATS * 4;     // 62464 B
    cudaFuncSetAttribute(gemm_tf32,        cudaFuncAttributeMaxDynamicSharedMemorySize, gemmSmem);
    cudaFuncSetAttribute(attn_energy_tf32, cudaFuncAttributeMaxDynamicSharedMemorySize, enerSmem);
    cudaFuncSetAttribute(attn_av_tf32,     cudaFuncAttributeMaxDynamicSharedMemorySize, avSmem);

    // 1. qkvr = x @ w_qkvr (raw)
    gemm_tf32<<<dim3(E4 / 128, MROWS / 128), 256, gemmSmem>>>(x, w_qkvr, qkvr, MROWS, E4, EMB);

    // 2. unpack (+ b_qkvr) -> q/k/v/r
    unpack_qkvr<<<4096, 256>>>(qkvr, b_qkvr);

    // 3. energy = q @ k^T (unscaled)
    attn_energy_tf32<<<dim3(SEQ / 128, SEQ / 128, BH), 256, enerSmem>>>(q, k, att);

    // 4. softmax / sqrt(768)
    softmax_scale<<<BH * SEQ, 128>>>(att);

    // 5. avraw = att @ v   (reuse g_qkvr as scratch)
    attn_av_tf32<<<dim3(1, SEQ / 128, BH), 256, avSmem>>>(att, v, qkvr);

    // 6. attout = avraw * r, merged to [b,n,e]
    rgate_merge<<<2048, 256>>>(qkvr, r, attout);

    // 7. proj = attout @ w_proj (raw)
    gemm_tf32<<<dim3(EMB / 128, MROWS / 128), 256, gemmSmem>>>(attout, w_proj, proj, MROWS, EMB, EMB);

    // 8. x1 = LN(proj + b_proj + x)
    resid_ln_bias<<<MROWS, 256>>>(proj, b_proj, x, ln1_g, ln1_b, x1);

    // 9. ffh = x1 @ w_ff1 (raw)
    gemm_tf32<<<dim3(E4 / 128, MROWS / 128), 256, gemmSmem>>>(x1, w_ff1, ffh, MROWS, E4, EMB);

    // 10. ffh = gelu(ffh + b_ff1)
    bias_gelu<<<8192, 256>>>(ffh, b_ff1);

    // 11. ff = ffh @ w_ff2 (raw)
    gemm_tf32<<<dim3(EMB / 128, MROWS / 128), 256, gemmSmem>>>(ffh, w_ff2, ff, MROWS, EMB, E4);

    // 12. out = LN(ff + b_ff2 + x1)
    resid_ln_bias<<<MROWS, 256>>>(ff, b_ff2, x1, ln2_g, ln2_b, out);
}

// round 15
// speedup vs baseline: 4.4116x; 3.1276x over previous
#include <cuda_runtime.h>
#include <cuda_fp16.h>
#include <cstdint>
#include <mma.h>
#include <math.h>

using namespace nvcuda;

// ---------------------------------------------------------------------------
// EncoderBlock: B=8, N=1024, E=768, H=8, d=96
// fp16 wmma (m16n16k16) GEMMs, fp32 accumulate; cp.async double-buffered.
// (tcgen05 unavailable: harness PTX target is compute_103, ptxas rejects it.)
// ---------------------------------------------------------------------------

#define Bb    8
#define SEQ   1024
#define EMB   768
#define HEADS 8
#define HD    96
#define MROWS (Bb * SEQ)     // 8192
#define E4    (4 * EMB)      // 3072
#define BH    (Bb * HEADS)   // 64

// fp32 scratch
__device__ float g_qkvr  [(size_t)MROWS * E4];   // qkvr raw; reused as AV-raw
__device__ float g_r     [(size_t)BH * SEQ * HD];
__device__ float g_att   [(size_t)BH * SEQ * SEQ];   // fp32 energy
__device__ float g_proj  [(size_t)MROWS * EMB];
__device__ float g_x1    [(size_t)MROWS * EMB];
__device__ float g_ffh   [(size_t)MROWS * E4];
__device__ float g_ff    [(size_t)MROWS * EMB];
// fp16 operands
__device__ __half g_xh    [(size_t)MROWS * EMB];
__device__ __half g_wqh   [(size_t)EMB * E4];
__device__ __half g_wph   [(size_t)EMB * EMB];
__device__ __half g_wf1h  [(size_t)EMB * E4];
__device__ __half g_wf2h  [(size_t)E4 * EMB];
__device__ __half g_qh    [(size_t)BH * SEQ * HD];
__device__ __half g_kh    [(size_t)BH * SEQ * HD];
__device__ __half g_vh    [(size_t)BH * SEQ * HD];
__device__ __half g_atth  [(size_t)BH * SEQ * SEQ];
__device__ __half g_aoh   [(size_t)MROWS * EMB];    // attout half
__device__ __half g_x1h   [(size_t)MROWS * EMB];
__device__ __half g_ffhh  [(size_t)MROWS * E4];

// ---------------------------------------------------------------------------
// cp.async helpers
// ---------------------------------------------------------------------------
__device__ __forceinline__ void cp_async16(void* smem_dst, const void* gsrc) {
    unsigned int s = (unsigned int)__cvta_generic_to_shared(smem_dst);
    asm volatile("cp.async.cg.shared.global [%0], [%1], 16;\n" :: "r"(s), "l"(gsrc));
}
__device__ __forceinline__ void cp_commit() {
    asm volatile("cp.async.commit_group;\n");
}
__device__ __forceinline__ void cp_wait1() {
    asm volatile("cp.async.wait_group 1;\n");
}
__device__ __forceinline__ void cp_wait0() {
    asm volatile("cp.async.wait_group 0;\n");
}

// ---------------------------------------------------------------------------
// fp32 -> fp16 convert (n % 8 == 0)
// ---------------------------------------------------------------------------
__global__ __launch_bounds__(256) void f2h(
    const float* __restrict__ s, __half* __restrict__ d, size_t n)
{
    for (size_t i = ((size_t)blockIdx.x * blockDim.x + threadIdx.x) * 8;
         i < n; i += (size_t)gridDim.x * blockDim.x * 8) {
        float4 a = *(const float4*)&s[i];
        float4 b = *(const float4*)&s[i + 4];
        __half2 h0 = __floats2half2_rn(a.x, a.y);
        __half2 h1 = __floats2half2_rn(a.z, a.w);
        __half2 h2 = __floats2half2_rn(b.x, b.y);
        __half2 h3 = __floats2half2_rn(b.z, b.w);
        uint4 o;
        o.x = *(unsigned*)&h0; o.y = *(unsigned*)&h1;
        o.z = *(unsigned*)&h2; o.w = *(unsigned*)&h3;
        *(uint4*)&d[i] = o;
    }
}

// ---------------------------------------------------------------------------
// fp16 GEMM: C[M,N](fp32) = A_h[M,K] @ B_h[K,N]
// 128x128 tile, BK=32, 2-stage cp.async, 8 warps (32x64 each), m16n16k16.
// ---------------------------------------------------------------------------
__global__ __launch_bounds__(256) void gemm_h(
    const __half* __restrict__ A, const __half* __restrict__ B,
    float* __restrict__ C, int Md, int Nd, int Kd)
{
    __shared__ __half As[2][128][40];   // 20480 B
    __shared__ __half Bs[2][32][136];   // 17408 B

    const int tid = threadIdx.x;
    const int warpId = tid >> 5;
    const int warpM = warpId >> 1;      // 0..3 -> 32 rows
    const int warpN = warpId & 1;       // 0..1 -> 64 cols
    const int rowStart = blockIdx.y * 128;
    const int colStart = blockIdx.x * 128;

    wmma::fragment<wmma::accumulator, 16, 16, 16, float> acc[2][4];
#pragma unroll
    for (int i = 0; i < 2; i++)
#pragma unroll
        for (int j = 0; j < 4; j++) wmma::fill_fragment(acc[i][j], 0.0f);

    const int ntiles = Kd >> 5;

    auto load_tile = [&](int t, int buf) {
        int kt = t << 5;
        // A tile 128x32 half = 512 x16B chunks, 2/thread
#pragma unroll
        for (int l = 0; l < 2; l++) {
            int c = tid + l * 256;
            int row = c >> 2;
            int k8 = (c & 3) * 8;
            cp_async16(&As[buf][row][k8],
                       &A[(size_t)(rowStart + row) * Kd + kt + k8]);
        }
        // B tile 32x128 half = 512 chunks, 2/thread
#pragma unroll
        for (int l = 0; l < 2; l++) {
            int c = tid + l * 256;
            int kr = c >> 4;
            int n8 = (c & 15) * 8;
            cp_async16(&Bs[buf][kr][n8],
                       &B[(size_t)(kt + kr) * Nd + colStart + n8]);
        }
        cp_commit();
    };

    load_tile(0, 0);

    for (int t = 0; t < ntiles; t++) {
        if (t + 1 < ntiles) { load_tile(t + 1, (t + 1) & 1); cp_wait1(); }
        else                { cp_wait0(); }
        __syncthreads();

        const int buf = t & 1;
#pragma unroll
        for (int kk = 0; kk < 32; kk += 16) {
            wmma::fragment<wmma::matrix_a, 16, 16, 16, __half, wmma::row_major> af[2];
            wmma::fragment<wmma::matrix_b, 16, 16, 16, __half, wmma::row_major> bf[4];
#pragma unroll
            for (int i = 0; i < 2; i++)
                wmma::load_matrix_sync(af[i], &As[buf][warpM * 32 + i * 16][kk], 40);
#pragma unroll
            for (int j = 0; j < 4; j++)
                wmma::load_matrix_sync(bf[j], &Bs[buf][kk][warpN * 64 + j * 16], 136);
#pragma unroll
            for (int i = 0; i < 2; i++)
#pragma unroll
                for (int j = 0; j < 4; j++)
                    wmma::mma_sync(acc[i][j], af[i], bf[j], acc[i][j]);
        }
        __syncthreads();
    }

#pragma unroll
    for (int i = 0; i < 2; i++)
#pragma unroll
        for (int j = 0; j < 4; j++)
            wmma::store_matrix_sync(
                &C[(size_t)(rowStart + warpM * 32 + i * 16) * Nd +
                   colStart + warpN * 64 + j * 16],
                acc[i][j], Nd, wmma::mem_row_major);
}

// ---------------------------------------------------------------------------
// energy[bh][i][j] = Q[bh][i][:].K[bh][j][:]  (NT, Kdim=96, fp16, fp32 out)
// ---------------------------------------------------------------------------
__global__ __launch_bounds__(256) void attn_energy_h(
    const __half* __restrict__ Q, const __half* __restrict__ K,
    float* __restrict__ Eout)
{
    __shared__ __half Qs[2][128][40];
    __shared__ __half Ks[2][128][40];

    const int tid = threadIdx.x;
    const int warpId = tid >> 5;
    const int warpM = warpId >> 1;
    const int warpN = warpId & 1;
    const int rowStart = blockIdx.y * 128;
    const int colStart = blockIdx.x * 128;
    const int bh = blockIdx.z;

    const __half* Qb = Q + (size_t)bh * SEQ * HD;
    const __half* Kb = K + (size_t)bh * SEQ * HD;

    wmma::fragment<wmma::accumulator, 16, 16, 16, float> acc[2][4];
#pragma unroll
    for (int i = 0; i < 2; i++)
#pragma unroll
        for (int j = 0; j < 4; j++) wmma::fill_fragment(acc[i][j], 0.0f);

    const int ntiles = HD >> 5;   // 3

    auto load_tile = [&](int t, int buf) {
        int kt = t << 5;
#pragma unroll
        for (int l = 0; l < 2; l++) {
            int c = tid + l * 256;
            int row = c >> 2;
            int k8 = (c & 3) * 8;
            cp_async16(&Qs[buf][row][k8],
                       &Qb[(size_t)(rowStart + row) * HD + kt + k8]);
            cp_async16(&Ks[buf][row][k8],
                       &Kb[(size_t)(colStart + row) * HD + kt + k8]);
        }
        cp_commit();
    };

    load_tile(0, 0);

    for (int t = 0; t < ntiles; t++) {
        if (t + 1 < ntiles) { load_tile(t + 1, (t + 1) & 1); cp_wait1(); }
        else                { cp_wait0(); }
        __syncthreads();

        const int buf = t & 1;
#pragma unroll
        for (int kk = 0; kk < 32; kk += 16) {
            wmma::fragment<wmma::matrix_a, 16, 16, 16, __half, wmma::row_major> af[2];
            wmma::fragment<wmma::matrix_b, 16, 16, 16, __half, wmma::col_major> bf[4];
#pragma unroll
            for (int i = 0; i < 2; i++)
                wmma::load_matrix_sync(af[i], &Qs[buf][warpM * 32 + i * 16][kk], 40);
#pragma unroll
            for (int j = 0; j < 4; j++)
                wmma::load_matrix_sync(bf[j], &Ks[buf][warpN * 64 + j * 16][kk], 40);
#pragma unroll
            for (int i = 0; i < 2; i++)
#pragma unroll
                for (int j = 0; j < 4; j++)
                    wmma::mma_sync(acc[i][j], af[i], bf[j], acc[i][j]);
        }
        __syncthreads();
    }

    float* Eb = Eout + (size_t)bh * SEQ * SEQ;
#pragma unroll
    for (int i = 0; i < 2; i++)
#pragma unroll
        for (int j = 0; j < 4; j++)
            wmma::store_matrix_sync(
                &Eb[(size_t)(rowStart + warpM * 32 + i * 16) * SEQ +
                    colStart + warpN * 64 + j * 16],
                acc[i][j], SEQ, wmma::mem_row_major);
}

// ---------------------------------------------------------------------------
// avraw[bh][n][d] = att_h[bh][n][:] @ V_h[bh][:][d]  (M=1024,N=96,K=1024)
// ---------------------------------------------------------------------------
__global__ __launch_bounds__(256) void attn_av_h(
    const __half* __restrict__ att, const __half* __restrict__ V,
    float* __restrict__ avraw)
{
    __shared__ __half As[2][128][40];
    __shared__ __half Bs[2][32][104];

    const int tid = threadIdx.x;
    const int warpId = tid >> 5;
    const int warpM = warpId >> 1;      // 0..3
    const int warpN = warpId & 1;       // 0..1 -> 48 cols
    const int rowStart = blockIdx.y * 128;
    const int bh = blockIdx.z;

    const __half* Ab = att + (size_t)bh * SEQ * SEQ;
    const __half* Vb = V + (size_t)bh * SEQ * HD;

    wmma::fragment<wmma::accumulator, 16, 16, 16, float> acc[2][3];
#pragma unroll
    for (int i = 0; i < 2; i++)
#pragma unroll
        for (int j = 0; j < 3; j++) wmma::fill_fragment(acc[i][j], 0.0f);

    const int ntiles = SEQ >> 5;   // 32

    auto load_tile = [&](int t, int buf) {
        int kt = t << 5;
#pragma unroll
        for (int l = 0; l < 2; l++) {
            int c = tid + l * 256;
            int row = c >> 2;
            int k8 = (c & 3) * 8;
            cp_async16(&As[buf][row][k8],
                       &Ab[(size_t)(rowStart + row) * SEQ + kt + k8]);
        }
        // V tile 32x96 half = 384 x16B chunks
        for (int c = tid; c < 384; c += 256) {
            int kr = c / 12;
            int n8 = (c % 12) * 8;
            cp_async16(&Bs[buf][kr][n8],
                       &Vb[(size_t)(kt + kr) * HD + n8]);
        }
        cp_commit();
    };

    load_tile(0, 0);

    for (int t = 0; t < ntiles; t++) {
        if (t + 1 < ntiles) { load_tile(t + 1, (t + 1) & 1); cp_wait1(); }
        else                { cp_wait0(); }
        __syncthreads();

        const int buf = t & 1;
#pragma unroll
        for (int kk = 0; kk < 32; kk += 16) {
            wmma::fragment<wmma::matrix_a, 16, 16, 16, __half, wmma::row_major> af[2];
            wmma::fragment<wmma::matrix_b, 16, 16, 16, __half, wmma::row_major> bf[3];
#pragma unroll
            for (int i = 0; i < 2; i++)
                wmma::load_matrix_sync(af[i], &As[buf][warpM * 32 + i * 16][kk], 40);
#pragma unroll
            for (int j = 0; j < 3; j++)
                wmma::load_matrix_sync(bf[j], &Bs[buf][kk][warpN * 48 + j * 16], 104);
#pragma unroll
            for (int i = 0; i < 2; i++)
#pragma unroll
                for (int j = 0; j < 3; j++)
                    wmma::mma_sync(acc[i][j], af[i], bf[j], acc[i][j]);
        }
        __syncthreads();
    }

    float* Sb = avraw + (size_t)bh * SEQ * HD;
#pragma unroll
    for (int i = 0; i < 2; i++)
#pragma unroll
        for (int j = 0; j < 3; j++)
            wmma::store_matrix_sync(
                &Sb[(size_t)(rowStart + warpM * 32 + i * 16) * HD +
                    warpN * 48 + j * 16],
                acc[i][j], HD, wmma::mem_row_major);
}

// ---------------------------------------------------------------------------
// Unpack qkvr raw (+bias) -> q/k/v (half), r (fp32)
// col = (h*96 + dd)*4 + s
// ---------------------------------------------------------------------------
__global__ void unpack_qkvr(const float* __restrict__ qkvr,
                            const float* __restrict__ bias)
{
    const size_t total = (size_t)MROWS * E4;
    for (size_t idx = (size_t)blockIdx.x * blockDim.x + threadIdx.x;
         idx < total; idx += (size_t)gridDim.x * blockDim.x) {
        int row = (int)(idx / E4);
        int col = (int)(idx % E4);
        int s  = col & 3;
        int t  = col >> 2;
        int h  = t / HD;
        int dd = t - h * HD;
        int b  = row >> 10;
        int n  = row & 1023;
        size_t dst = ((size_t)(b * HEADS + h) * SEQ + n) * HD + dd;
        float val = qkvr[idx] + bias[col];
        if      (s == 0) g_qh[dst] = __float2half_rn(val);
        else if (s == 1) g_kh[dst] = __float2half_rn(val);
        else if (s == 2) g_vh[dst] = __float2half_rn(val);
        else             g_r[dst] = val;
    }
}

// ---------------------------------------------------------------------------
// Row softmax of UNSCALED fp32 logits -> fp16 probabilities (NO /sqrt(768);
// that scale is folded into rgate_merge to keep att in fp16 normal range).
// ---------------------------------------------------------------------------
__global__ __launch_bounds__(128) void softmax_h(
    const float* __restrict__ att, __half* __restrict__ atth)
{
    __shared__ float red[128];
    const int tid = threadIdx.x;
    const float4* rowp = (const float4*)(att + (size_t)blockIdx.x * SEQ);
    __half* orow = atth + (size_t)blockIdx.x * SEQ;

    float4 a = rowp[tid];
    float4 b = rowp[tid + 128];
    float m = fmaxf(fmaxf(fmaxf(a.x, a.y), fmaxf(a.z, a.w)),
                    fmaxf(fmaxf(b.x, b.y), fmaxf(b.z, b.w)));
    red[tid] = m;
    __syncthreads();
    for (int off = 64; off > 0; off >>= 1) {
        if (tid < off) red[tid] = fmaxf(red[tid], red[tid + off]);
        __syncthreads();
    }
    m = red[0];
    __syncthreads();

    a.x = expf(a.x - m); a.y = expf(a.y - m); a.z = expf(a.z - m); a.w = expf(a.w - m);
    b.x = expf(b.x - m); b.y = expf(b.y - m); b.z = expf(b.z - m); b.w = expf(b.w - m);
    float s = a.x + a.y + a.z + a.w + b.x + b.y + b.z + b.w;
    red[tid] = s;
    __syncthreads();
    for (int off = 64; off > 0; off >>= 1) {
        if (tid < off) red[tid] += red[tid + off];
        __syncthreads();
    }
    const float inv = 1.0f / red[0];
    __half2 h0 = __floats2half2_rn(a.x * inv, a.y * inv);
    __half2 h1 = __floats2half2_rn(a.z * inv, a.w * inv);
    __half2 h2 = __floats2half2_rn(b.x * inv, b.y * inv);
    __half2 h3 = __floats2half2_rn(b.z * inv, b.w * inv);
    uint2 o0; o0.x = *(unsigned*)&h0; o0.y = *(unsigned*)&h1;
    uint2 o1; o1.x = *(unsigned*)&h2; o1.y = *(unsigned*)&h3;
    *(uint2*)&orow[tid * 4] = o0;
    *(uint2*)&orow[512 + tid * 4] = o1;
}

// ---------------------------------------------------------------------------
// r-gate + /sqrt(768) + head merge -> attout (half, feeds proj GEMM)
// ---------------------------------------------------------------------------
__global__ __launch_bounds__(256) void rgate_merge_h(
    const float* __restrict__ avraw, const float* __restrict__ R,
    __half* __restrict__ outh)
{
    const float c = 0.036084391824351615f;   // 1/sqrt(768)
    const size_t total4 = (size_t)MROWS * EMB / 4;
    for (size_t idx = (size_t)blockIdx.x * blockDim.x + threadIdx.x;
         idx < total4; idx += (size_t)gridDim.x * blockDim.x) {
        int row = (int)(idx / 192);
        int c4  = (int)(idx % 192);
        int col = c4 * 4;
        int h  = col / HD;
        int d  = col - h * HD;
        int b  = row >> 10;
        int n  = row & 1023;
        size_t src = (((size_t)(b * HEADS + h) * SEQ + n) * HD + d) / 4;
        float4 p = ((const float4*)avraw)[src];
        float4 g = ((const float4*)R)[src];
        __half2 h0 = __floats2half2_rn(p.x * g.x * c, p.y * g.y * c);
        __half2 h1 = __floats2half2_rn(p.z * g.z * c, p.w * g.w * c);
        uint2 o; o.x = *(unsigned*)&h0; o.y = *(unsigned*)&h1;
        *(uint2*)&outh[idx * 4] = o;
    }
}

// ---------------------------------------------------------------------------
// ffh_h = half(gelu(ffh + b_ff1)), exact erf
// ---------------------------------------------------------------------------
__global__ __launch_bounds__(256) void bias_gelu_h(
    const float* __restrict__ ffh, const float* __restrict__ bias,
    __half* __restrict__ outh)
{
    const size_t total4 = (size_t)MROWS * E4 / 4;
    for (size_t idx = (size_t)blockIdx.x * blockDim.x + threadIdx.x;
         idx < total4; idx += (size_t)gridDim.x * blockDim.x) {
        int c4 = (int)(idx % (E4 / 4));
        float4 bv = ((const float4*)bias)[c4];
        float4 v = ((const float4*)ffh)[idx];
        v.x += bv.x; v.y += bv.y; v.z += bv.z; v.w += bv.w;
        v.x = 0.5f * v.x * (1.0f + erff(v.x * 0.70710678118654752f));
        v.y = 0.5f * v.y * (1.0f + erff(v.y * 0.70710678118654752f));
        v.z = 0.5f * v.z * (1.0f + erff(v.z * 0.70710678118654752f));
        v.w = 0.5f * v.w * (1.0f + erff(v.w * 0.70710678118654752f));
        __half2 h0 = __floats2half2_rn(v.x, v.y);
        __half2 h1 = __floats2half2_rn(v.z, v.w);
        uint2 o; o.x = *(unsigned*)&h0; o.y = *(unsigned*)&h1;
        *(uint2*)&outh[idx * 4] = o;
    }
}

// ---------------------------------------------------------------------------
// out = LayerNorm(a + bias2 + b) * g + beta; optional half copy for next GEMM
// ---------------------------------------------------------------------------
__global__ __launch_bounds__(256) void resid_ln_bias(
    const float* __restrict__ a, const float* __restrict__ bias2,
    const float* __restrict__ b,
    const float* __restrict__ g, const float* __restrict__ beta,
    float* __restrict__ out, __half* __restrict__ outh)
{
    __shared__ float red[256];
    const int tid = threadIdx.x;
    const size_t base = (size_t)blockIdx.x * EMB;

    float y[3];
    float s = 0.0f;
#pragma unroll
    for (int i = 0; i < 3; i++) {
        int j = tid + i * 256;
        y[i] = a[base + j] + bias2[j] + b[base + j];
        s += y[i];
    }
    red[tid] = s;
    __syncthreads();
    for (int off = 128; off > 0; off >>= 1) {
        if (tid < off) red[tid] += red[tid + off];
        __syncthreads();
    }
    const float mu = red[0] * (1.0f / EMB);
    __syncthreads();

    s = 0.0f;
#pragma unroll
    for (int i = 0; i < 3; i++) {
        float d = y[i] - mu;
        s += d * d;
    }
    red[tid] = s;
    __syncthreads();
    for (int off = 128; off > 0; off >>= 1) {
        if (tid < off) red[tid] += red[tid + off];
        __syncthreads();
    }
    const float inv = rsqrtf(red[0] * (1.0f / EMB) + 1e-5f);
#pragma unroll
    for (int i = 0; i < 3; i++) {
        int j = tid + i * 256;
        float val = (y[i] - mu) * inv * g[j] + beta[j];
        out[base + j] = val;
        if (outh) outh[base + j] = __float2half_rn(val);
    }
}

// ---------------------------------------------------------------------------
extern "C" void kernel_launch(void* const* d_in, const int* in_sizes, int n_in,
                              void* d_out, int out_size)
{
    (void)in_sizes; (void)n_in; (void)out_size;

    const float* x      = (const float*)d_in[0];
    const float* w_qkvr = (const float*)d_in[1];
    const float* b_qkvr = (const float*)d_in[2];
    const float* w_proj = (const float*)d_in[3];
    const float* b_proj = (const float*)d_in[4];
    const float* ln1_g  = (const float*)d_in[5];
    const float* ln1_b  = (const float*)d_in[6];
    const float* w_ff1  = (const float*)d_in[7];
    const float* b_ff1  = (const float*)d_in[8];
    const float* w_ff2  = (const float*)d_in[9];
    const float* b_ff2  = (const float*)d_in[10];
    const float* ln2_g  = (const float*)d_in[11];
    const float* ln2_b  = (const float*)d_in[12];
    float* out = (float*)d_out;

    float *qkvr, *r, *att, *proj, *x1, *ffh, *ff;
    __half *xh, *wqh, *wph, *wf1h, *wf2h, *qh, *kh, *vh, *atth, *aoh, *x1h, *ffhh;
    cudaGetSymbolAddress((void**)&qkvr, g_qkvr);
    cudaGetSymbolAddress((void**)&r,    g_r);
    cudaGetSymbolAddress((void**)&att,  g_att);
    cudaGetSymbolAddress((void**)&proj, g_proj);
    cudaGetSymbolAddress((void**)&x1,   g_x1);
    cudaGetSymbolAddress((void**)&ffh,  g_ffh);
    cudaGetSymbolAddress((void**)&ff,   g_ff);
    cudaGetSymbolAddress((void**)&xh,   g_xh);
    cudaGetSymbolAddress((void**)&wqh,  g_wqh);
    cudaGetSymbolAddress((void**)&wph,  g_wph);
    cudaGetSymbolAddress((void**)&wf1h, g_wf1h);
    cudaGetSymbolAddress((void**)&wf2h, g_wf2h);
    cudaGetSymbolAddress((void**)&qh,   g_qh);
    cudaGetSymbolAddress((void**)&kh,   g_kh);
    cudaGetSymbolAddress((void**)&vh,   g_vh);
    cudaGetSymbolAddress((void**)&atth, g_atth);
    cudaGetSymbolAddress((void**)&aoh,  g_aoh);
    cudaGetSymbolAddress((void**)&x1h,  g_x1h);
    cudaGetSymbolAddress((void**)&ffhh, g_ffhh);

    // 0. fp32 -> fp16 operand conversion
    f2h<<<1024, 256>>>(x,      xh,   (size_t)MROWS * EMB);
    f2h<<<1024, 256>>>(w_qkvr, wqh,  (size_t)EMB * E4);
    f2h<<<512,  256>>>(w_proj, wph,  (size_t)EMB * EMB);
    f2h<<<1024, 256>>>(w_ff1,  wf1h, (size_t)EMB * E4);
    f2h<<<1024, 256>>>(w_ff2,  wf2h, (size_t)E4 * EMB);

    // 1. qkvr = x @ w_qkvr (raw fp32)
    gemm_h<<<dim3(E4 / 128, MROWS / 128), 256>>>(xh, wqh, qkvr, MROWS, E4, EMB);

    // 2. unpack (+ b_qkvr) -> q/k/v half, r fp32
    unpack_qkvr<<<4096, 256>>>(qkvr, b_qkvr);

    // 3. energy = q @ k^T (unscaled, fp32)
    attn_energy_h<<<dim3(SEQ / 128, SEQ / 128, BH), 256>>>(qh, kh, att);

    // 4. att_h = softmax(energy)  (scale deferred)
    softmax_h<<<BH * SEQ, 128>>>(att, atth);

    // 5. avraw = att_h @ v_h  (fp32, reuse g_qkvr)
    attn_av_h<<<dim3(1, SEQ / 128, BH), 256>>>(atth, vh, qkvr);

    // 6. attout_h = avraw * r / sqrt(768), merged to [b,n,e]
    rgate_merge_h<<<2048, 256>>>(qkvr, r, aoh);

    // 7. proj = attout_h @ w_proj (fp32)
    gemm_h<<<dim3(EMB / 128, MROWS / 128), 256>>>(aoh, wph, proj, MROWS, EMB, EMB);

    // 8. x1 = LN(proj + b_proj + x)  (+ half copy)
    resid_ln_bias<<<MROWS, 256>>>(proj, b_proj, x, ln1_g, ln1_b, x1, x1h);

    // 9. ffh = x1_h @ w_ff1 (fp32)
    gemm_h<<<dim3(E4 / 128, MROWS / 128), 256>>>(x1h, wf1h, ffh, MROWS, E4, EMB);

    // 10. ffh_h = half(gelu(ffh + b_ff1))
    bias_gelu_h<<<8192, 256>>>(ffh, b_ff1, ffhh);

    // 11. ff = ffh_h @ w_ff2 (fp32)
    gemm_h<<<dim3(EMB / 128, MROWS / 128), 256>>>(ffhh, wf2h, ff, MROWS, EMB, E4);

    // 12. out = LN(ff + b_ff2 + x1)
    resid_ln_bias<<<MROWS, 256>>>(ff, b_ff2, x1, ln2_g, ln2_b, out, (__half*)nullptr);
}

// round 17
// speedup vs baseline: 4.4276x; 1.0036x over previous
#include <cuda_runtime.h>
#include <cuda_fp16.h>
#include <cstdint>
#include <mma.h>
#include <math.h>

using namespace nvcuda;

// ---------------------------------------------------------------------------
// EncoderBlock: B=8, N=1024, E=768, H=8, d=96
// fp16 wmma (m16n16k16) GEMMs, fp32 accumulate.
// 4-stage cp.async pipeline, ONE __syncthreads per mainloop iteration.
// ---------------------------------------------------------------------------

#define Bb    8
#define SEQ   1024
#define EMB   768
#define HEADS 8
#define HD    96
#define MROWS (Bb * SEQ)     // 8192
#define E4    (4 * EMB)      // 3072
#define BH    (Bb * HEADS)   // 64

// dynamic smem sizes (bytes)
#define GEMMH_SMEM  ((4*128*40 + 4*32*136) * 2)   // 75776
#define ENERH_SMEM  ((4*128*40 + 4*128*40) * 2)   // 81920
#define AVH_SMEM    ((4*128*40 + 4*32*104) * 2)   // 67584

// fp32 scratch
__device__ float g_qkvr  [(size_t)MROWS * E4];   // qkvr raw; reused as AV-raw
__device__ float g_r     [(size_t)BH * SEQ * HD];
__device__ float g_att   [(size_t)BH * SEQ * SEQ];   // fp32 energy
__device__ float g_proj  [(size_t)MROWS * EMB];
__device__ float g_x1    [(size_t)MROWS * EMB];
__device__ float g_ffh   [(size_t)MROWS * E4];
__device__ float g_ff    [(size_t)MROWS * EMB];
// fp16 operands
__device__ __half g_xh    [(size_t)MROWS * EMB];
__device__ __half g_wqh   [(size_t)EMB * E4];
__device__ __half g_wph   [(size_t)EMB * EMB];
__device__ __half g_wf1h  [(size_t)EMB * E4];
__device__ __half g_wf2h  [(size_t)E4 * EMB];
__device__ __half g_qh    [(size_t)BH * SEQ * HD];
__device__ __half g_kh    [(size_t)BH * SEQ * HD];
__device__ __half g_vh    [(size_t)BH * SEQ * HD];
__device__ __half g_atth  [(size_t)BH * SEQ * SEQ];
__device__ __half g_aoh   [(size_t)MROWS * EMB];    // attout half
__device__ __half g_x1h   [(size_t)MROWS * EMB];
__device__ __half g_ffhh  [(size_t)MROWS * E4];

// ---------------------------------------------------------------------------
// cp.async helpers
// ---------------------------------------------------------------------------
__device__ __forceinline__ void cp_async16(void* smem_dst, const void* gsrc) {
    unsigned int s = (unsigned int)__cvta_generic_to_shared(smem_dst);
    asm volatile("cp.async.cg.shared.global [%0], [%1], 16;\n" :: "r"(s), "l"(gsrc));
}
__device__ __forceinline__ void cp_commit() {
    asm volatile("cp.async.commit_group;\n");
}
__device__ __forceinline__ void cp_wait2() {
    asm volatile("cp.async.wait_group 2;\n");
}
__device__ __forceinline__ void cp_wait1() {
    asm volatile("cp.async.wait_group 1;\n");
}
__device__ __forceinline__ void cp_wait0() {
    asm volatile("cp.async.wait_group 0;\n");
}
// iter t: after issuing group t+2, wait until group t is complete
__device__ __forceinline__ void cp_wait_for(int t, int ntiles) {
    if (t + 2 < ntiles)      cp_wait2();
    else if (t + 1 < ntiles) cp_wait1();
    else                     cp_wait0();
}

// ---------------------------------------------------------------------------
// fp32 -> fp16 convert (n % 8 == 0)
// ---------------------------------------------------------------------------
__global__ __launch_bounds__(256) void f2h(
    const float* __restrict__ s, __half* __restrict__ d, size_t n)
{
    for (size_t i = ((size_t)blockIdx.x * blockDim.x + threadIdx.x) * 8;
         i < n; i += (size_t)gridDim.x * blockDim.x * 8) {
        float4 a = *(const float4*)&s[i];
        float4 b = *(const float4*)&s[i + 4];
        __half2 h0 = __floats2half2_rn(a.x, a.y);
        __half2 h1 = __floats2half2_rn(a.z, a.w);
        __half2 h2 = __floats2half2_rn(b.x, b.y);
        __half2 h3 = __floats2half2_rn(b.z, b.w);
        uint4 o;
        o.x = *(unsigned*)&h0; o.y = *(unsigned*)&h1;
        o.z = *(unsigned*)&h2; o.w = *(unsigned*)&h3;
        *(uint4*)&d[i] = o;
    }
}

// ---------------------------------------------------------------------------
// fp16 GEMM: C[M,N](fp32) = A_h[M,K] @ B_h[K,N]
// 128x128 tile, BK=32, 4-stage cp.async, 8 warps (32x64), one sync/iter.
// ---------------------------------------------------------------------------
__global__ __launch_bounds__(256) void gemm_h(
    const __half* __restrict__ A, const __half* __restrict__ B,
    float* __restrict__ C, int Md, int Nd, int Kd)
{
    extern __shared__ __half hsm[];
    __half (*As)[128][40] = reinterpret_cast<__half(*)[128][40]>(hsm);
    __half (*Bs)[32][136] = reinterpret_cast<__half(*)[32][136]>(hsm + 4*128*40);

    const int tid = threadIdx.x;
    const int warpId = tid >> 5;
    const int warpM = warpId >> 1;      // 0..3 -> 32 rows
    const int warpN = warpId & 1;       // 0..1 -> 64 cols
    const int rowStart = blockIdx.y * 128;
    const int colStart = blockIdx.x * 128;

    wmma::fragment<wmma::accumulator, 16, 16, 16, float> acc[2][4];
#pragma unroll
    for (int i = 0; i < 2; i++)
#pragma unroll
        for (int j = 0; j < 4; j++) wmma::fill_fragment(acc[i][j], 0.0f);

    const int ntiles = Kd >> 5;

    auto load_tile = [&](int t) {
        const int buf = t & 3;
        const int kt = t << 5;
#pragma unroll
        for (int l = 0; l < 2; l++) {
            int c = tid + l * 256;
            int row = c >> 2;
            int k8 = (c & 3) * 8;
            cp_async16(&As[buf][row][k8],
                       &A[(size_t)(rowStart + row) * Kd + kt + k8]);
        }
#pragma unroll
        for (int l = 0; l < 2; l++) {
            int c = tid + l * 256;
            int kr = c >> 4;
            int n8 = (c & 15) * 8;
            cp_async16(&Bs[buf][kr][n8],
                       &B[(size_t)(kt + kr) * Nd + colStart + n8]);
        }
        cp_commit();
    };

    load_tile(0);
    if (ntiles > 1) load_tile(1);

    for (int t = 0; t < ntiles; t++) {
        if (t + 2 < ntiles) load_tile(t + 2);
        cp_wait_for(t, ntiles);
        __syncthreads();

        const int buf = t & 3;
#pragma unroll
        for (int kk = 0; kk < 32; kk += 16) {
            wmma::fragment<wmma::matrix_a, 16, 16, 16, __half, wmma::row_major> af[2];
            wmma::fragment<wmma::matrix_b, 16, 16, 16, __half, wmma::row_major> bf[4];
#pragma unroll
            for (int i = 0; i < 2; i++)
                wmma::load_matrix_sync(af[i], &As[buf][warpM * 32 + i * 16][kk], 40);
#pragma unroll
            for (int j = 0; j < 4; j++)
                wmma::load_matrix_sync(bf[j], &Bs[buf][kk][warpN * 64 + j * 16], 136);
#pragma unroll
            for (int i = 0; i < 2; i++)
#pragma unroll
                for (int j = 0; j < 4; j++)
                    wmma::mma_sync(acc[i][j], af[i], bf[j], acc[i][j]);
        }
    }

#pragma unroll
    for (int i = 0; i < 2; i++)
#pragma unroll
        for (int j = 0; j < 4; j++)
            wmma::store_matrix_sync(
                &C[(size_t)(rowStart + warpM * 32 + i * 16) * Nd +
                   colStart + warpN * 64 + j * 16],
                acc[i][j], Nd, wmma::mem_row_major);
}

// ---------------------------------------------------------------------------
// energy[bh][i][j] = Q[bh][i][:].K[bh][j][:]  (NT, Kdim=96, fp16, fp32 out)
// ---------------------------------------------------------------------------
__global__ __launch_bounds__(256) void attn_energy_h(
    const __half* __restrict__ Q, const __half* __restrict__ K,
    float* __restrict__ Eout)
{
    extern __shared__ __half hsm[];
    __half (*Qs)[128][40] = reinterpret_cast<__half(*)[128][40]>(hsm);
    __half (*Ks)[128][40] = reinterpret_cast<__half(*)[128][40]>(hsm + 4*128*40);

    const int tid = threadIdx.x;
    const int warpId = tid >> 5;
    const int warpM = warpId >> 1;
    const int warpN = warpId & 1;
    const int rowStart = blockIdx.y * 128;
    const int colStart = blockIdx.x * 128;
    const int bh = blockIdx.z;

    const __half* Qb = Q + (size_t)bh * SEQ * HD;
    const __half* Kb = K + (size_t)bh * SEQ * HD;

    wmma::fragment<wmma::accumulator, 16, 16, 16, float> acc[2][4];
#pragma unroll
    for (int i = 0; i < 2; i++)
#pragma unroll
        for (int j = 0; j < 4; j++) wmma::fill_fragment(acc[i][j], 0.0f);

    const int ntiles = HD >> 5;   // 3

    auto load_tile = [&](int t) {
        const int buf = t & 3;
        const int kt = t << 5;
#pragma unroll
        for (int l = 0; l < 2; l++) {
            int c = tid + l * 256;
            int row = c >> 2;
            int k8 = (c & 3) * 8;
            cp_async16(&Qs[buf][row][k8],
                       &Qb[(size_t)(rowStart + row) * HD + kt + k8]);
            cp_async16(&Ks[buf][row][k8],
                       &Kb[(size_t)(colStart + row) * HD + kt + k8]);
        }
        cp_commit();
    };

    load_tile(0);
    if (ntiles > 1) load_tile(1);

    for (int t = 0; t < ntiles; t++) {
        if (t + 2 < ntiles) load_tile(t + 2);
        cp_wait_for(t, ntiles);
        __syncthreads();

        const int buf = t & 3;
#pragma unroll
        for (int kk = 0; kk < 32; kk += 16) {
            wmma::fragment<wmma::matrix_a, 16, 16, 16, __half, wmma::row_major> af[2];
            wmma::fragment<wmma::matrix_b, 16, 16, 16, __half, wmma::col_major> bf[4];
#pragma unroll
            for (int i = 0; i < 2; i++)
                wmma::load_matrix_sync(af[i], &Qs[buf][warpM * 32 + i * 16][kk], 40);
#pragma unroll
            for (int j = 0; j < 4; j++)
                wmma::load_matrix_sync(bf[j], &Ks[buf][warpN * 64 + j * 16][kk], 40);
#pragma unroll
            for (int i = 0; i < 2; i++)
#pragma unroll
                for (int j = 0; j < 4; j++)
                    wmma::mma_sync(acc[i][j], af[i], bf[j], acc[i][j]);
        }
    }

    float* Eb = Eout + (size_t)bh * SEQ * SEQ;
#pragma unroll
    for (int i = 0; i < 2; i++)
#pragma unroll
        for (int j = 0; j < 4; j++)
            wmma::store_matrix_sync(
                &Eb[(size_t)(rowStart + warpM * 32 + i * 16) * SEQ +
                    colStart + warpN * 64 + j * 16],
                acc[i][j], SEQ, wmma::mem_row_major);
}

// ---------------------------------------------------------------------------
// avraw[bh][n][d] = att_h[bh][n][:] @ V_h[bh][:][d]  (M=1024,N=96,K=1024)
// ---------------------------------------------------------------------------
__global__ __launch_bounds__(256) void attn_av_h(
    const __half* __restrict__ att, const __half* __restrict__ V,
    float* __restrict__ avraw)
{
    extern __shared__ __half hsm[];
    __half (*As)[128][40] = reinterpret_cast<__half(*)[128][40]>(hsm);
    __half (*Bs)[32][104] = reinterpret_cast<__half(*)[32][104]>(hsm + 4*128*40);

    const int tid = threadIdx.x;
    const int warpId = tid >> 5;
    const int warpM = warpId >> 1;      // 0..3
    const int warpN = warpId & 1;       // 0..1 -> 48 cols
    const int rowStart = blockIdx.y * 128;
    const int bh = blockIdx.z;

    const __half* Ab = att + (size_t)bh * SEQ * SEQ;
    const __half* Vb = V + (size_t)bh * SEQ * HD;

    wmma::fragment<wmma::accumulator, 16, 16, 16, float> acc[2][3];
#pragma unroll
    for (int i = 0; i < 2; i++)
#pragma unroll
        for (int j = 0; j < 3; j++) wmma::fill_fragment(acc[i][j], 0.0f);

    const int ntiles = SEQ >> 5;   // 32

    auto load_tile = [&](int t) {
        const int buf = t & 3;
        const int kt = t << 5;
#pragma unroll
        for (int l = 0; l < 2; l++) {
            int c = tid + l * 256;
            int row = c >> 2;
            int k8 = (c & 3) * 8;
            cp_async16(&As[buf][row][k8],
                       &Ab[(size_t)(rowStart + row) * SEQ + kt + k8]);
        }
        for (int c = tid; c < 384; c += 256) {
            int kr = c / 12;
            int n8 = (c % 12) * 8;
            cp_async16(&Bs[buf][kr][n8],
                       &Vb[(size_t)(kt + kr) * HD + n8]);
        }
        cp_commit();
    };

    load_tile(0);
    if (ntiles > 1) load_tile(1);

    for (int t = 0; t < ntiles; t++) {
        if (t + 2 < ntiles) load_tile(t + 2);
        cp_wait_for(t, ntiles);
        __syncthreads();

        const int buf = t & 3;
#pragma unroll
        for (int kk = 0; kk < 32; kk += 16) {
            wmma::fragment<wmma::matrix_a, 16, 16, 16, __half, wmma::row_major> af[2];
            wmma::fragment<wmma::matrix_b, 16, 16, 16, __half, wmma::row_major> bf[3];
#pragma unroll
            for (int i = 0; i < 2; i++)
                wmma::load_matrix_sync(af[i], &As[buf][warpM * 32 + i * 16][kk], 40);
#pragma unroll
            for (int j = 0; j < 3; j++)
                wmma::load_matrix_sync(bf[j], &Bs[buf][kk][warpN * 48 + j * 16], 104);
#pragma unroll
            for (int i = 0; i < 2; i++)
#pragma unroll
                for (int j = 0; j < 3; j++)
                    wmma::mma_sync(acc[i][j], af[i], bf[j], acc[i][j]);
        }
    }

    float* Sb = avraw + (size_t)bh * SEQ * HD;
#pragma unroll
    for (int i = 0; i < 2; i++)
#pragma unroll
        for (int j = 0; j < 3; j++)
            wmma::store_matrix_sync(
                &Sb[(size_t)(rowStart + warpM * 32 + i * 16) * HD +
                    warpN * 48 + j * 16],
                acc[i][j], HD, wmma::mem_row_major);
}

// ---------------------------------------------------------------------------
// Unpack qkvr raw (+bias) -> q/k/v (half), r (fp32)
// ---------------------------------------------------------------------------
__global__ void unpack_qkvr(const float* __restrict__ qkvr,
                            const float* __restrict__ bias)
{
    const size_t total = (size_t)MROWS * E4;
    for (size_t idx = (size_t)blockIdx.x * blockDim.x + threadIdx.x;
         idx < total; idx += (size_t)gridDim.x * blockDim.x) {
        int row = (int)(idx / E4);
        int col = (int)(idx % E4);
        int s  = col & 3;
        int t  = col >> 2;
        int h  = t / HD;
        int dd = t - h * HD;
        int b  = row >> 10;
        int n  = row & 1023;
        size_t dst = ((size_t)(b * HEADS + h) * SEQ + n) * HD + dd;
        float val = qkvr[idx] + bias[col];
        if      (s == 0) g_qh[dst] = __float2half_rn(val);
        else if (s == 1) g_kh[dst] = __float2half_rn(val);
        else if (s == 2) g_vh[dst] = __float2half_rn(val);
        else             g_r[dst] = val;
    }
}

// ---------------------------------------------------------------------------
// Row softmax of UNSCALED fp32 logits -> fp16 probabilities (NO /sqrt(768);
// folded into rgate_merge to keep att in fp16 normal range).
// ---------------------------------------------------------------------------
__global__ __launch_bounds__(128) void softmax_h(
    const float* __restrict__ att, __half* __restrict__ atth)
{
    __shared__ float red[128];
    const int tid = threadIdx.x;
    const float4* rowp = (const float4*)(att + (size_t)blockIdx.x * SEQ);
    __half* orow = atth + (size_t)blockIdx.x * SEQ;

    float4 a = rowp[tid];
    float4 b = rowp[tid + 128];
    float m = fmaxf(fmaxf(fmaxf(a.x, a.y), fmaxf(a.z, a.w)),
                    fmaxf(fmaxf(b.x, b.y), fmaxf(b.z, b.w)));
    red[tid] = m;
    __syncthreads();
    for (int off = 64; off > 0; off >>= 1) {
        if (tid < off) red[tid] = fmaxf(red[tid], red[tid + off]);
        __syncthreads();
    }
    m = red[0];
    __syncthreads();

    a.x = expf(a.x - m); a.y = expf(a.y - m); a.z = expf(a.z - m); a.w = expf(a.w - m);
    b.x = expf(b.x - m); b.y = expf(b.y - m); b.z = expf(b.z - m); b.w = expf(b.w - m);
    float s = a.x + a.y + a.z + a.w + b.x + b.y + b.z + b.w;
    red[tid] = s;
    __syncthreads();
    for (int off = 64; off > 0; off >>= 1) {
        if (tid < off) red[tid] += red[tid + off];
        __syncthreads();
    }
    const float inv = 1.0f / red[0];
    __half2 h0 = __floats2half2_rn(a.x * inv, a.y * inv);
    __half2 h1 = __floats2half2_rn(a.z * inv, a.w * inv);
    __half2 h2 = __floats2half2_rn(b.x * inv, b.y * inv);
    __half2 h3 = __floats2half2_rn(b.z * inv, b.w * inv);
    uint2 o0; o0.x = *(unsigned*)&h0; o0.y = *(unsigned*)&h1;
    uint2 o1; o1.x = *(unsigned*)&h2; o1.y = *(unsigned*)&h3;
    *(uint2*)&orow[tid * 4] = o0;
    *(uint2*)&orow[512 + tid * 4] = o1;
}

// ---------------------------------------------------------------------------
// r-gate + /sqrt(768) + head merge -> attout (half, feeds proj GEMM)
// ---------------------------------------------------------------------------
__global__ __launch_bounds__(256) void rgate_merge_h(
    const float* __restrict__ avraw, const float* __restrict__ R,
    __half* __restrict__ outh)
{
    const float c = 0.036084391824351615f;   // 1/sqrt(768)
    const size_t total4 = (size_t)MROWS * EMB / 4;
    for (size_t idx = (size_t)blockIdx.x * blockDim.x + threadIdx.x;
         idx < total4; idx += (size_t)gridDim.x * blockDim.x) {
        int row = (int)(idx / 192);
        int c4  = (int)(idx % 192);
        int col = c4 * 4;
        int h  = col / HD;
        int d  = col - h * HD;
        int b  = row >> 10;
        int n  = row & 1023;
        size_t src = (((size_t)(b * HEADS + h) * SEQ + n) * HD + d) / 4;
        float4 p = ((const float4*)avraw)[src];
        float4 g = ((const float4*)R)[src];
        __half2 h0 = __floats2half2_rn(p.x * g.x * c, p.y * g.y * c);
        __half2 h1 = __floats2half2_rn(p.z * g.z * c, p.w * g.w * c);
        uint2 o; o.x = *(unsigned*)&h0; o.y = *(unsigned*)&h1;
        *(uint2*)&outh[idx * 4] = o;
    }
}

// ---------------------------------------------------------------------------
// ffh_h = half(gelu(ffh + b_ff1)), exact erf
// ---------------------------------------------------------------------------
__global__ __launch_bounds__(256) void bias_gelu_h(
    const float* __restrict__ ffh, const float* __restrict__ bias,
    __half* __restrict__ outh)
{
    const size_t total4 = (size_t)MROWS * E4 / 4;
    for (size_t idx = (size_t)blockIdx.x * blockDim.x + threadIdx.x;
         idx < total4; idx += (size_t)gridDim.x * blockDim.x) {
        int c4 = (int)(idx % (E4 / 4));
        float4 bv = ((const float4*)bias)[c4];
        float4 v = ((const float4*)ffh)[idx];
        v.x += bv.x; v.y += bv.y; v.z += bv.z; v.w += bv.w;
        v.x = 0.5f * v.x * (1.0f + erff(v.x * 0.70710678118654752f));
        v.y = 0.5f * v.y * (1.0f + erff(v.y * 0.70710678118654752f));
        v.z = 0.5f * v.z * (1.0f + erff(v.z * 0.70710678118654752f));
        v.w = 0.5f * v.w * (1.0f + erff(v.w * 0.70710678118654752f));
        __half2 h0 = __floats2half2_rn(v.x, v.y);
        __half2 h1 = __floats2half2_rn(v.z, v.w);
        uint2 o; o.x = *(unsigned*)&h0; o.y = *(unsigned*)&h1;
        *(uint2*)&outh[idx * 4] = o;
    }
}

// ---------------------------------------------------------------------------
// out = LayerNorm(a + bias2 + b) * g + beta; optional half copy for next GEMM
// ---------------------------------------------------------------------------
__global__ __launch_bounds__(256) void resid_ln_bias(
    const float* __restrict__ a, const float* __restrict__ bias2,
    const float* __restrict__ b,
    const float* __restrict__ g, const float* __restrict__ beta,
    float* __restrict__ out, __half* __restrict__ outh)
{
    __shared__ float red[256];
    const int tid = threadIdx.x;
    const size_t base = (size_t)blockIdx.x * EMB;

    float y[3];
    float s = 0.0f;
#pragma unroll
    for (int i = 0; i < 3; i++) {
        int j = tid + i * 256;
        y[i] = a[base + j] + bias2[j] + b[base + j];
        s += y[i];
    }
    red[tid] = s;
    __syncthreads();
    for (int off = 128; off > 0; off >>= 1) {
        if (tid < off) red[tid] += red[tid + off];
        __syncthreads();
    }
    const float mu = red[0] * (1.0f / EMB);
    __syncthreads();

    s = 0.0f;
#pragma unroll
    for (int i = 0; i < 3; i++) {
        float d = y[i] - mu;
        s += d * d;
    }
    red[tid] = s;
    __syncthreads();
    for (int off = 128; off > 0; off >>= 1) {
        if (tid < off) red[tid] += red[tid + off];
        __syncthreads();
    }
    const float inv = rsqrtf(red[0] * (1.0f / EMB) + 1e-5f);
#pragma unroll
    for (int i = 0; i < 3; i++) {
        int j = tid + i * 256;
        float val = (y[i] - mu) * inv * g[j] + beta[j];
        out[base + j] = val;
        if (outh) outh[base + j] = __float2half_rn(val);
    }
}

// ---------------------------------------------------------------------------
extern "C" void kernel_launch(void* const* d_in, const int* in_sizes, int n_in,
                              void* d_out, int out_size)
{
    (void)in_sizes; (void)n_in; (void)out_size;

    const float* x      = (const float*)d_in[0];
    const float* w_qkvr = (const float*)d_in[1];
    const float* b_qkvr = (const float*)d_in[2];
    const float* w_proj = (const float*)d_in[3];
    const float* b_proj = (const float*)d_in[4];
    const float* ln1_g  = (const float*)d_in[5];
    const float* ln1_b  = (const float*)d_in[6];
    const float* w_ff1  = (const float*)d_in[7];
    const float* b_ff1  = (const float*)d_in[8];
    const float* w_ff2  = (const float*)d_in[9];
    const float* b_ff2  = (const float*)d_in[10];
    const float* ln2_g  = (const float*)d_in[11];
    const float* ln2_b  = (const float*)d_in[12];
    float* out = (float*)d_out;

    float *qkvr, *r, *att, *proj, *x1, *ffh, *ff;
    __half *xh, *wqh, *wph, *wf1h, *wf2h, *qh, *kh, *vh, *atth, *aoh, *x1h, *ffhh;
    cudaGetSymbolAddress((void**)&qkvr, g_qkvr);
    cudaGetSymbolAddress((void**)&r,    g_r);
    cudaGetSymbolAddress((void**)&att,  g_att);
    cudaGetSymbolAddress((void**)&proj, g_proj);
    cudaGetSymbolAddress((void**)&x1,   g_x1);
    cudaGetSymbolAddress((void**)&ffh,  g_ffh);
    cudaGetSymbolAddress((void**)&ff,   g_ff);
    cudaGetSymbolAddress((void**)&xh,   g_xh);
    cudaGetSymbolAddress((void**)&wqh,  g_wqh);
    cudaGetSymbolAddress((void**)&wph,  g_wph);
    cudaGetSymbolAddress((void**)&wf1h, g_wf1h);
    cudaGetSymbolAddress((void**)&wf2h, g_wf2h);
    cudaGetSymbolAddress((void**)&qh,   g_qh);
    cudaGetSymbolAddress((void**)&kh,   g_kh);
    cudaGetSymbolAddress((void**)&vh,   g_vh);
    cudaGetSymbolAddress((void**)&atth, g_atth);
    cudaGetSymbolAddress((void**)&aoh,  g_aoh);
    cudaGetSymbolAddress((void**)&x1h,  g_x1h);
    cudaGetSymbolAddress((void**)&ffhh, g_ffhh);

    cudaFuncSetAttribute(gemm_h,        cudaFuncAttributeMaxDynamicSharedMemorySize, GEMMH_SMEM);
    cudaFuncSetAttribute(attn_energy_h, cudaFuncAttributeMaxDynamicSharedMemorySize, ENERH_SMEM);
    cudaFuncSetAttribute(attn_av_h,     cudaFuncAttributeMaxDynamicSharedMemorySize, AVH_SMEM);

    // 0. fp32 -> fp16 operand conversion
    f2h<<<1024, 256>>>(x,      xh,   (size_t)MROWS * EMB);
    f2h<<<1024, 256>>>(w_qkvr, wqh,  (size_t)EMB * E4);
    f2h<<<512,  256>>>(w_proj, wph,  (size_t)EMB * EMB);
    f2h<<<1024, 256>>>(w_ff1,  wf1h, (size_t)EMB * E4);
    f2h<<<1024, 256>>>(w_ff2,  wf2h, (size_t)E4 * EMB);

    // 1. qkvr = x @ w_qkvr (raw fp32)
    gemm_h<<<dim3(E4 / 128, MROWS / 128), 256, GEMMH_SMEM>>>(xh, wqh, qkvr, MROWS, E4, EMB);

    // 2. unpack (+ b_qkvr) -> q/k/v half, r fp32
    unpack_qkvr<<<4096, 256>>>(qkvr, b_qkvr);

    // 3. energy = q @ k^T (unscaled, fp32)
    attn_energy_h<<<dim3(SEQ / 128, SEQ / 128, BH), 256, ENERH_SMEM>>>(qh, kh, att);

    // 4. att_h = softmax(energy)  (scale deferred)
    softmax_h<<<BH * SEQ, 128>>>(att, atth);

    // 5. avraw = att_h @ v_h  (fp32, reuse g_qkvr)
    attn_av_h<<<dim3(1, SEQ / 128, BH), 256, AVH_SMEM>>>(atth, vh, qkvr);

    // 6. attout_h = avraw * r / sqrt(768), merged to [b,n,e]
    rgate_merge_h<<<2048, 256>>>(qkvr, r, aoh);

    // 7. proj = attout_h @ w_proj (fp32)
    gemm_h<<<dim3(EMB / 128, MROWS / 128), 256, GEMMH_SMEM>>>(aoh, wph, proj, MROWS, EMB, EMB);

    // 8. x1 = LN(proj + b_proj + x)  (+ half copy)
    resid_ln_bias<<<MROWS, 256>>>(proj, b_proj, x, ln1_g, ln1_b, x1, x1h);

    // 9. ffh = x1_h @ w_ff1 (fp32)
    gemm_h<<<dim3(E4 / 128, MROWS / 128), 256, GEMMH_SMEM>>>(x1h, wf1h, ffh, MROWS, E4, EMB);

    // 10. ffh_h = half(gelu(ffh + b_ff1))
    bias_gelu_h<<<8192, 256>>>(ffh, b_ff1, ffhh);

    // 11. ff = ffh_h @ w_ff2 (fp32)
    gemm_h<<<dim3(EMB / 128, MROWS / 128), 256, GEMMH_SMEM>>>(ffhh, wf2h, ff, MROWS, EMB, E4);

    // 12. out = LN(ff + b_ff2 + x1)
    resid_ln_bias<<<MROWS, 256>>>(ff, b_ff2, x1, ln2_g, ln2_b, out, (__half*)nullptr);
}